// round 7
// baseline (speedup 1.0000x reference)
#include <cuda_runtime.h>
#include <cuda_bf16.h>
#include <math.h>
#include <stdint.h>

#define D_MODEL 1024
#define HEADS 16
#define HEAD_DIM 64
#define BATCH 4
#define SEQ 2048
#define MTOT (BATCH * SEQ) /* 8192 */
#define WSZ (D_MODEL * D_MODEL)

typedef __nv_bfloat16 bf16;

// ---- scratch (static __device__; allocation APIs forbidden) ----
__device__ bf16 g_xh[(size_t)MTOT * D_MODEL];
__device__ bf16 g_xl[(size_t)MTOT * D_MODEL];
__device__ bf16 g_qkvh[(size_t)3 * MTOT * D_MODEL];
__device__ bf16 g_qkvl[(size_t)3 * MTOT * D_MODEL];
__device__ bf16 g_mh[(size_t)MTOT * D_MODEL];
__device__ bf16 g_ml[(size_t)MTOT * D_MODEL];
__device__ bf16 g_wh[(size_t)3 * WSZ];
__device__ bf16 g_wl[(size_t)3 * WSZ];

// ============================ PTX helpers ============================
__device__ __forceinline__ uint32_t smem_u32(const void* p) {
    uint32_t a;
    asm("{ .reg .u64 t; cvta.to.shared.u64 t, %1; cvt.u32.u64 %0, t; }"
        : "=r"(a) : "l"(p));
    return a;
}
__device__ __forceinline__ void cp16(uint32_t s, const void* g) {
    asm volatile("cp.async.cg.shared.global [%0], [%1], 16;" :: "r"(s), "l"(g) : "memory");
}
__device__ __forceinline__ void cp_commit() {
    asm volatile("cp.async.commit_group;" ::: "memory");
}
template <int N> __device__ __forceinline__ void cp_wait() {
    asm volatile("cp.async.wait_group %0;" :: "n"(N) : "memory");
}
__device__ __forceinline__ void ldsm4(uint32_t* r, uint32_t addr) {
    asm volatile("ldmatrix.sync.aligned.m8n8.x4.shared.b16 {%0,%1,%2,%3}, [%4];"
                 : "=r"(r[0]), "=r"(r[1]), "=r"(r[2]), "=r"(r[3]) : "r"(addr));
}
__device__ __forceinline__ void ldsm4t(uint32_t* r, uint32_t addr) {
    asm volatile("ldmatrix.sync.aligned.m8n8.x4.trans.shared.b16 {%0,%1,%2,%3}, [%4];"
                 : "=r"(r[0]), "=r"(r[1]), "=r"(r[2]), "=r"(r[3]) : "r"(addr));
}
__device__ __forceinline__ void mma16816(float* c, const uint32_t* a,
                                         uint32_t b0, uint32_t b1) {
    asm volatile(
        "mma.sync.aligned.m16n8k16.row.col.f32.bf16.bf16.f32 "
        "{%0,%1,%2,%3},{%4,%5,%6,%7},{%8,%9},{%0,%1,%2,%3};"
        : "+f"(c[0]), "+f"(c[1]), "+f"(c[2]), "+f"(c[3])
        : "r"(a[0]), "r"(a[1]), "r"(a[2]), "r"(a[3]), "r"(b0), "r"(b1));
}
__device__ __forceinline__ uint32_t bf2(bf16 a, bf16 b) {
    __nv_bfloat162 t; t.x = a; t.y = b;
    return *(uint32_t*)&t;
}

// ============================ mma.sync GEMM ============================
// C = A @ W, 3-term bf16 split. 128x128 tile, BK=32, 8 warps (4x2),
// 2-stage cp.async. Term-separated passes: acc reuse distance = 16 MMAs.
#define BK 32
#define NCHUNK (D_MODEL / BK) /* 32 */
#define ROW_B 80
#define TILE_B (128 * ROW_B)
#define STAGE_B (4 * TILE_B)
#define GEMM_SMEM (2 * STAGE_B) /* 81920 */

__global__ __launch_bounds__(256, 2) void gemm_mma(
    const bf16* __restrict__ Ah, const bf16* __restrict__ Al,
    const bf16* __restrict__ BhAll, const bf16* __restrict__ BlAll,
    float* __restrict__ Cf, bf16* __restrict__ ChAll, bf16* __restrict__ ClAll,
    float scale0)
{
    extern __shared__ char smem[];
    const uint32_t sb = smem_u32(smem);
    const int tid = threadIdx.x;
    const int wid = tid >> 5, lane = tid & 31;
    const int wm = wid & 3, wn = wid >> 2;
    const int rowBase = blockIdx.y * 128;
    const int colBase = blockIdx.x * 128;

    const bf16* Bh = BhAll + (size_t)blockIdx.z * WSZ;
    const bf16* Bl = BlAll + (size_t)blockIdx.z * WSZ;

    const bf16* src[4] = {
        Ah + (size_t)rowBase * D_MODEL, Al + (size_t)rowBase * D_MODEL,
        Bh + (size_t)colBase * D_MODEL, Bl + (size_t)colBase * D_MODEL};

    float acc[2][8][4];
#pragma unroll
    for (int mi = 0; mi < 2; mi++)
#pragma unroll
        for (int ni = 0; ni < 8; ni++)
#pragma unroll
            for (int j = 0; j < 4; j++) acc[mi][ni][j] = 0.f;

    auto load_chunk = [&](int c, int s) {
        const uint32_t tb = sb + s * STAGE_B;
        const int kofs = c * BK;
#pragma unroll
        for (int t = 0; t < 4; t++) {
#pragma unroll
            for (int i = 0; i < 2; i++) {
                int f = i * 256 + tid;
                int row = f >> 2, cc = f & 3;
                cp16(tb + t * TILE_B + row * ROW_B + cc * 16,
                     src[t] + (size_t)row * D_MODEL + kofs + cc * 8);
            }
        }
    };

    const uint32_t lrow = lane & 15, lcol = lane >> 4;

    load_chunk(0, 0);
    cp_commit();

    for (int c = 0; c < NCHUNK; c++) {
        if (c + 1 < NCHUNK) {
            load_chunk(c + 1, (c + 1) & 1);
            cp_commit();
            cp_wait<1>();
        } else {
            cp_wait<0>();
        }
        __syncthreads();

        const uint32_t tb = sb + (c & 1) * STAGE_B;
        const uint32_t aTh = tb, aTl = tb + TILE_B;
        const uint32_t bTh = tb + 2 * TILE_B, bTl = tb + 3 * TILE_B;

#pragma unroll
        for (int k16 = 0; k16 < 2; k16++) {
            const uint32_t kb = k16 * 32;
            const uint32_t arow = (wm * 32 + lrow) * ROW_B + kb + lcol * 16;
            uint32_t a_h[2][4], a_l[2][4], bh[4][4], bl[4][4];
            ldsm4(a_h[0], aTh + arow);
            ldsm4(a_h[1], aTh + arow + 16 * ROW_B);
            ldsm4(a_l[0], aTl + arow);
            ldsm4(a_l[1], aTl + arow + 16 * ROW_B);
#pragma unroll
            for (int nb = 0; nb < 4; nb++)
                ldsm4(bh[nb], bTh + (wn * 64 + nb * 16 + lrow) * ROW_B + kb + lcol * 16);
#pragma unroll
            for (int nb = 0; nb < 4; nb++)
                ldsm4(bl[nb], bTl + (wn * 64 + nb * 16 + lrow) * ROW_B + kb + lcol * 16);
            // pass 1: Ah x Bh (each acc hit once)
#pragma unroll
            for (int nb = 0; nb < 4; nb++)
#pragma unroll
                for (int mi = 0; mi < 2; mi++) {
                    mma16816(acc[mi][2 * nb], a_h[mi], bh[nb][0], bh[nb][2]);
                    mma16816(acc[mi][2 * nb + 1], a_h[mi], bh[nb][1], bh[nb][3]);
                }
            // pass 2: Al x Bh
#pragma unroll
            for (int nb = 0; nb < 4; nb++)
#pragma unroll
                for (int mi = 0; mi < 2; mi++) {
                    mma16816(acc[mi][2 * nb], a_l[mi], bh[nb][0], bh[nb][2]);
                    mma16816(acc[mi][2 * nb + 1], a_l[mi], bh[nb][1], bh[nb][3]);
                }
            // pass 3: Ah x Bl
#pragma unroll
            for (int nb = 0; nb < 4; nb++)
#pragma unroll
                for (int mi = 0; mi < 2; mi++) {
                    mma16816(acc[mi][2 * nb], a_h[mi], bl[nb][0], bl[nb][2]);
                    mma16816(acc[mi][2 * nb + 1], a_h[mi], bl[nb][1], bl[nb][3]);
                }
        }
        __syncthreads();
    }

    // Epilogue
    const int g = lane >> 2, t4 = lane & 3;
    if (ChAll) {
        bf16* Ch = ChAll + (size_t)blockIdx.z * MTOT * D_MODEL;
        bf16* Cl = ClAll + (size_t)blockIdx.z * MTOT * D_MODEL;
        const float sc = (blockIdx.z == 0) ? scale0 : 1.0f;
#pragma unroll
        for (int mi = 0; mi < 2; mi++)
#pragma unroll
            for (int ni = 0; ni < 8; ni++) {
                int r = rowBase + wm * 32 + mi * 16 + g;
                int col = colBase + wn * 64 + ni * 8 + t4 * 2;
#pragma unroll
                for (int half = 0; half < 2; half++) {
                    float v0 = acc[mi][ni][2 * half] * sc;
                    float v1 = acc[mi][ni][2 * half + 1] * sc;
                    bf16 h0 = __float2bfloat16(v0);
                    bf16 h1 = __float2bfloat16(v1);
                    bf16 l0 = __float2bfloat16(v0 - __bfloat162float(h0));
                    bf16 l1 = __float2bfloat16(v1 - __bfloat162float(h1));
                    size_t o = (size_t)(r + 8 * half) * D_MODEL + col;
                    *(uint32_t*)&Ch[o] = bf2(h0, h1);
                    *(uint32_t*)&Cl[o] = bf2(l0, l1);
                }
            }
    } else {
#pragma unroll
        for (int mi = 0; mi < 2; mi++)
#pragma unroll
            for (int ni = 0; ni < 8; ni++) {
                int r = rowBase + wm * 32 + mi * 16 + g;
                int col = colBase + wn * 64 + ni * 8 + t4 * 2;
                *(float2*)&Cf[(size_t)r * D_MODEL + col] =
                    make_float2(acc[mi][ni][0], acc[mi][ni][1]);
                *(float2*)&Cf[(size_t)(r + 8) * D_MODEL + col] =
                    make_float2(acc[mi][ni][2], acc[mi][ni][3]);
            }
    }
}

// ==================== conversion kernels ====================
__global__ __launch_bounds__(256) void split_kernel(
    const float* __restrict__ in, bf16* __restrict__ hi, bf16* __restrict__ lo, int n2)
{
    int i = blockIdx.x * blockDim.x + threadIdx.x;
    if (i >= n2) return;
    float2 v = ((const float2*)in)[i];
    bf16 h0 = __float2bfloat16(v.x);
    bf16 l0 = __float2bfloat16(v.x - __bfloat162float(h0));
    bf16 h1 = __float2bfloat16(v.y);
    bf16 l1 = __float2bfloat16(v.y - __bfloat162float(h1));
    ((uint32_t*)hi)[i] = bf2(h0, h1);
    ((uint32_t*)lo)[i] = bf2(l0, l1);
}

__global__ __launch_bounds__(256) void wT_split3(
    const float* __restrict__ W0, const float* __restrict__ W1,
    const float* __restrict__ W2, bf16* __restrict__ Th, bf16* __restrict__ Tl)
{
    const float* W = (blockIdx.z == 0) ? W0 : (blockIdx.z == 1) ? W1 : W2;
    Th += (size_t)blockIdx.z * WSZ;
    Tl += (size_t)blockIdx.z * WSZ;
    __shared__ float t[32][33];
    int nx = blockIdx.x * 32 + threadIdx.x;
#pragma unroll
    for (int j = 0; j < 32; j += 8)
        t[threadIdx.y + j][threadIdx.x] =
            W[(size_t)(blockIdx.y * 32 + threadIdx.y + j) * D_MODEL + nx];
    __syncthreads();
    int k = blockIdx.y * 32 + threadIdx.x;
#pragma unroll
    for (int j = 0; j < 32; j += 8) {
        int n = blockIdx.x * 32 + threadIdx.y + j;
        float v = t[threadIdx.x][threadIdx.y + j];
        bf16 h = __float2bfloat16(v);
        bf16 l = __float2bfloat16(v - __bfloat162float(h));
        Th[(size_t)n * D_MODEL + k] = h;
        Tl[(size_t)n * D_MODEL + k] = l;
    }
}

// ==================== tensor-core flash attention v3 ====================
// CTA: 128 threads (4 warps), 64 queries, one (b,h). 2 CTAs/SM.
// Single KV stage; phase-pipelined K/V loads. Term-separated MMA passes.
#define KROW 144
#define KTILE (128 * KROW)          /* 18432 */
#define ATTN_SMEM (4 * KTILE)       /* 73728: Kh,Kl,Vh,Vl */

__global__ __launch_bounds__(128, 2) void attn_mma(
    const bf16* __restrict__ Qh, const bf16* __restrict__ Ql,
    const bf16* __restrict__ Kh, const bf16* __restrict__ Kl,
    const bf16* __restrict__ Vh, const bf16* __restrict__ Vl,
    bf16* __restrict__ MH, bf16* __restrict__ ML)
{
    extern __shared__ char smraw[];
    const uint32_t sb = smem_u32(smraw);
    const int tid = threadIdx.x;
    const int wid = tid >> 5, lane = tid & 31;
    const uint32_t lrow = lane & 15, lcol = lane >> 4;
    const int g = lane >> 2, t4 = lane & 3;

    const int q0 = blockIdx.x * 64;
    const int h = blockIdx.y;
    const int b = blockIdx.z;
    const size_t qrow = (size_t)b * SEQ + q0;
    const size_t krow0 = (size_t)b * SEQ;
    const int hofs = h * HEAD_DIM;

    const uint32_t skh = sb, skl = sb + KTILE;
    const uint32_t svh = sb + 2 * KTILE, svl = sb + 3 * KTILE;

    auto load_k = [&](int t) {
        const size_t kr = krow0 + (size_t)t * 128;
#pragma unroll
        for (int i = 0; i < 16; i++) {
            int f = i * 128 + tid;
            int arr = f >> 10;
            int r = (f >> 3) & 127, cg = f & 7;
            const bf16* p = arr ? Kl : Kh;
            cp16(sb + arr * KTILE + r * KROW + cg * 16,
                 p + (kr + r) * D_MODEL + hofs + cg * 8);
        }
    };
    auto load_v = [&](int t) {
        const size_t kr = krow0 + (size_t)t * 128;
#pragma unroll
        for (int i = 0; i < 16; i++) {
            int f = i * 128 + tid;
            int arr = f >> 10;
            int r = (f >> 3) & 127, cg = f & 7;
            const bf16* p = arr ? Vl : Vh;
            cp16(sb + (2 + arr) * KTILE + r * KROW + cg * 16,
                 p + (kr + r) * D_MODEL + hofs + cg * 8);
        }
    };

    load_k(0); cp_commit();
    load_v(0); cp_commit();

    // ---- Q fragments direct from gmem ----
    uint32_t qhf[4][4], qlf[4][4];
    {
        const size_t r0 = qrow + wid * 16 + g;
        const int c0 = hofs + t4 * 2;
#pragma unroll
        for (int kc = 0; kc < 4; kc++) {
#pragma unroll
            for (int q = 0; q < 4; q++) {
                size_t r = r0 + ((q & 1) ? 8 : 0);
                int c = c0 + kc * 16 + ((q & 2) ? 8 : 0);
                qhf[kc][q] = *(const uint32_t*)&Qh[r * D_MODEL + c];
                qlf[kc][q] = *(const uint32_t*)&Ql[r * D_MODEL + c];
            }
        }
    }

    float o[8][4];
#pragma unroll
    for (int di = 0; di < 8; di++)
#pragma unroll
        for (int j = 0; j < 4; j++) o[di][j] = 0.f;
    float m_prev[2] = {-1e30f, -1e30f};
    float lsum[2] = {0.f, 0.f};

    const int NT = SEQ / 128;  // 16
    for (int t = 0; t < NT; t++) {
        cp_wait<1>();       // K_t landed
        __syncthreads();

        // ---- S = Q K^T, term-separated passes ----
        float s[16][4];
#pragma unroll
        for (int ni = 0; ni < 16; ni++)
#pragma unroll
            for (int j = 0; j < 4; j++) s[ni][j] = 0.f;

#pragma unroll
        for (int kc = 0; kc < 4; kc++) {
            uint32_t kf[8][4];
#pragma unroll
            for (int np = 0; np < 8; np++)
                ldsm4(kf[np], skh + (np * 16 + lrow) * KROW + kc * 32 + lcol * 16);
            // pass 1: Qh x Kh  (each s[ni] hit once)
#pragma unroll
            for (int ni = 0; ni < 16; ni++) {
                int np = ni >> 1, hl = ni & 1;
                mma16816(s[ni], qhf[kc], kf[np][hl], kf[np][hl + 2]);
            }
            // pass 2: Ql x Kh
#pragma unroll
            for (int ni = 0; ni < 16; ni++) {
                int np = ni >> 1, hl = ni & 1;
                mma16816(s[ni], qlf[kc], kf[np][hl], kf[np][hl + 2]);
            }
        }
#pragma unroll
        for (int kc = 0; kc < 4; kc++) {
            uint32_t kf[8][4];
#pragma unroll
            for (int np = 0; np < 8; np++)
                ldsm4(kf[np], skl + (np * 16 + lrow) * KROW + kc * 32 + lcol * 16);
            // pass 3: Qh x Kl
#pragma unroll
            for (int ni = 0; ni < 16; ni++) {
                int np = ni >> 1, hl = ni & 1;
                mma16816(s[ni], qhf[kc], kf[np][hl], kf[np][hl + 2]);
            }
        }
        __syncthreads();
        if (t + 1 < NT) { load_k(t + 1); cp_commit(); }

        // ---- online softmax (overlaps K_{t+1} load) ----
#pragma unroll
        for (int rg = 0; rg < 2; rg++) {
            float mx = -1e30f;
#pragma unroll
            for (int ni = 0; ni < 16; ni++)
                mx = fmaxf(mx, fmaxf(s[ni][2 * rg], s[ni][2 * rg + 1]));
            mx = fmaxf(mx, __shfl_xor_sync(0xffffffffu, mx, 1));
            mx = fmaxf(mx, __shfl_xor_sync(0xffffffffu, mx, 2));
            float mn = fmaxf(m_prev[rg], mx);
            float al = __expf(m_prev[rg] - mn);
            float sum = 0.f;
#pragma unroll
            for (int ni = 0; ni < 16; ni++) {
                float p0 = __expf(s[ni][2 * rg] - mn);
                float p1 = __expf(s[ni][2 * rg + 1] - mn);
                s[ni][2 * rg] = p0;
                s[ni][2 * rg + 1] = p1;
                sum += p0 + p1;
            }
            sum += __shfl_xor_sync(0xffffffffu, sum, 1);
            sum += __shfl_xor_sync(0xffffffffu, sum, 2);
            lsum[rg] = lsum[rg] * al + sum;
            m_prev[rg] = mn;
#pragma unroll
            for (int di = 0; di < 8; di++) {
                o[di][2 * rg] *= al;
                o[di][2 * rg + 1] *= al;
            }
        }

        cp_wait<1>();       // V_t landed
        __syncthreads();

        // ---- O += P V, term-separated passes ----
#pragma unroll
        for (int kc2 = 0; kc2 < 8; kc2++) {
            int j0 = 2 * kc2, j1 = j0 + 1;
            uint32_t ah[4], al4[4];
#pragma unroll
            for (int q = 0; q < 4; q++) {
                const float* sp = (q & 2) ? s[j1] : s[j0];
                float v0 = sp[(q & 1) * 2], v1 = sp[(q & 1) * 2 + 1];
                bf16 h0 = __float2bfloat16(v0);
                bf16 h1 = __float2bfloat16(v1);
                ah[q] = bf2(h0, h1);
                al4[q] = bf2(__float2bfloat16(v0 - __bfloat162float(h0)),
                             __float2bfloat16(v1 - __bfloat162float(h1)));
            }
            uint32_t vhf[4][4], vlf[4][4];
#pragma unroll
            for (int dp = 0; dp < 4; dp++) {
                uint32_t a = (kc2 * 16 + lrow) * KROW + (dp * 16 + lcol * 8) * 2;
                ldsm4t(vhf[dp], svh + a);
                ldsm4t(vlf[dp], svl + a);
            }
            // pass A: Ph x Vh  (each o[di] hit once)
#pragma unroll
            for (int di = 0; di < 8; di++) {
                int dp = di >> 1, off = (di & 1) * 2;
                mma16816(o[di], ah, vhf[dp][off], vhf[dp][off + 1]);
            }
            // pass B: Ph x Vl
#pragma unroll
            for (int di = 0; di < 8; di++) {
                int dp = di >> 1, off = (di & 1) * 2;
                mma16816(o[di], ah, vlf[dp][off], vlf[dp][off + 1]);
            }
            // pass C: Pl x Vh
#pragma unroll
            for (int di = 0; di < 8; di++) {
                int dp = di >> 1, off = (di & 1) * 2;
                mma16816(o[di], al4, vhf[dp][off], vhf[dp][off + 1]);
            }
        }
        __syncthreads();
        if (t + 1 < NT) { load_v(t + 1); cp_commit(); }
    }

    // ---- epilogue ----
    float inv_l[2] = {1.f / lsum[0], 1.f / lsum[1]};
#pragma unroll
    for (int di = 0; di < 8; di++) {
#pragma unroll
        for (int rg = 0; rg < 2; rg++) {
            float v0 = o[di][2 * rg] * inv_l[rg];
            float v1 = o[di][2 * rg + 1] * inv_l[rg];
            bf16 h0 = __float2bfloat16(v0);
            bf16 h1 = __float2bfloat16(v1);
            size_t idx = (qrow + wid * 16 + g + 8 * rg) * D_MODEL + hofs + di * 8 + t4 * 2;
            *(uint32_t*)&MH[idx] = bf2(h0, h1);
            *(uint32_t*)&ML[idx] = bf2(__float2bfloat16(v0 - __bfloat162float(h0)),
                                       __float2bfloat16(v1 - __bfloat162float(h1)));
        }
    }
}

// ---------------------------------------------------------------------------
extern "C" void kernel_launch(void* const* d_in, const int* in_sizes, int n_in,
                              void* d_out, int out_size)
{
    (void)in_sizes; (void)n_in; (void)out_size;
    const float* x    = (const float*)d_in[0];
    const float* W_q  = (const float*)d_in[1];
    const float* W_k  = (const float*)d_in[2];
    const float* W_v  = (const float*)d_in[3];
    const float* fc_o = (const float*)d_in[4];
    float* out = (float*)d_out;

    bf16 *xh, *xl, *qkvh, *qkvl, *mh, *ml, *wh, *wl;
    cudaGetSymbolAddress((void**)&xh, g_xh);
    cudaGetSymbolAddress((void**)&xl, g_xl);
    cudaGetSymbolAddress((void**)&qkvh, g_qkvh);
    cudaGetSymbolAddress((void**)&qkvl, g_qkvl);
    cudaGetSymbolAddress((void**)&mh, g_mh);
    cudaGetSymbolAddress((void**)&ml, g_ml);
    cudaGetSymbolAddress((void**)&wh, g_wh);
    cudaGetSymbolAddress((void**)&wl, g_wl);

    cudaFuncSetAttribute(gemm_mma, cudaFuncAttributeMaxDynamicSharedMemorySize, GEMM_SMEM);
    cudaFuncSetAttribute(attn_mma, cudaFuncAttributeMaxDynamicSharedMemorySize, ATTN_SMEM);

    const int n2_x = MTOT * D_MODEL / 2;
    dim3 wgrid(D_MODEL / 32, D_MODEL / 32, 3);
    dim3 wblk(32, 8);

    split_kernel<<<(n2_x + 255) / 256, 256>>>(x, xh, xl, n2_x);
    wT_split3<<<wgrid, wblk>>>(W_q, W_k, W_v, wh, wl);

    dim3 ggrid3(D_MODEL / 128, MTOT / 128, 3);
    gemm_mma<<<ggrid3, 256, GEMM_SMEM>>>(xh, xl, wh, wl, nullptr, qkvh, qkvl, 0.125f);

    const size_t PL = (size_t)MTOT * D_MODEL;
    dim3 attn_grid(SEQ / 64, HEADS, BATCH);
    attn_mma<<<attn_grid, 128, ATTN_SMEM>>>(qkvh, qkvl, qkvh + PL, qkvl + PL,
                                            qkvh + 2 * PL, qkvl + 2 * PL, mh, ml);

    dim3 wgrid1(D_MODEL / 32, D_MODEL / 32, 1);
    wT_split3<<<wgrid1, wblk>>>(fc_o, fc_o, fc_o, wh, wl);
    dim3 ggrid1(D_MODEL / 128, MTOT / 128, 1);
    gemm_mma<<<ggrid1, 256, GEMM_SMEM>>>(mh, ml, wh, wl, out, nullptr, nullptr, 1.0f);
}

// round 8
// speedup vs baseline: 1.0127x; 1.0127x over previous
#include <cuda_runtime.h>
#include <cuda_bf16.h>
#include <math.h>
#include <stdint.h>

#define D_MODEL 1024
#define HEADS 16
#define HEAD_DIM 64
#define BATCH 4
#define SEQ 2048
#define MTOT (BATCH * SEQ) /* 8192 */
#define WSZ (D_MODEL * D_MODEL)

typedef __nv_bfloat16 bf16;

// ---- scratch (static __device__; allocation APIs forbidden) ----
__device__ bf16 g_xh[(size_t)MTOT * D_MODEL];
__device__ bf16 g_xl[(size_t)MTOT * D_MODEL];
__device__ bf16 g_qkvh[(size_t)3 * MTOT * D_MODEL];
__device__ bf16 g_qkvl[(size_t)3 * MTOT * D_MODEL];
__device__ bf16 g_mh[(size_t)MTOT * D_MODEL];
__device__ bf16 g_ml[(size_t)MTOT * D_MODEL];
__device__ bf16 g_wh[(size_t)3 * WSZ];
__device__ bf16 g_wl[(size_t)3 * WSZ];

// ============================ PTX helpers ============================
__device__ __forceinline__ uint32_t smem_u32(const void* p) {
    uint32_t a;
    asm("{ .reg .u64 t; cvta.to.shared.u64 t, %1; cvt.u32.u64 %0, t; }"
        : "=r"(a) : "l"(p));
    return a;
}
__device__ __forceinline__ void cp16(uint32_t s, const void* g) {
    asm volatile("cp.async.cg.shared.global [%0], [%1], 16;" :: "r"(s), "l"(g) : "memory");
}
__device__ __forceinline__ void cp_commit() {
    asm volatile("cp.async.commit_group;" ::: "memory");
}
template <int N> __device__ __forceinline__ void cp_wait() {
    asm volatile("cp.async.wait_group %0;" :: "n"(N) : "memory");
}
__device__ __forceinline__ void ldsm4(uint32_t* r, uint32_t addr) {
    asm volatile("ldmatrix.sync.aligned.m8n8.x4.shared.b16 {%0,%1,%2,%3}, [%4];"
                 : "=r"(r[0]), "=r"(r[1]), "=r"(r[2]), "=r"(r[3]) : "r"(addr));
}
__device__ __forceinline__ void ldsm4t(uint32_t* r, uint32_t addr) {
    asm volatile("ldmatrix.sync.aligned.m8n8.x4.trans.shared.b16 {%0,%1,%2,%3}, [%4];"
                 : "=r"(r[0]), "=r"(r[1]), "=r"(r[2]), "=r"(r[3]) : "r"(addr));
}
__device__ __forceinline__ void mma16816(float* c, const uint32_t* a,
                                         uint32_t b0, uint32_t b1) {
    asm volatile(
        "mma.sync.aligned.m16n8k16.row.col.f32.bf16.bf16.f32 "
        "{%0,%1,%2,%3},{%4,%5,%6,%7},{%8,%9},{%0,%1,%2,%3};"
        : "+f"(c[0]), "+f"(c[1]), "+f"(c[2]), "+f"(c[3])
        : "r"(a[0]), "r"(a[1]), "r"(a[2]), "r"(a[3]), "r"(b0), "r"(b1));
}
__device__ __forceinline__ uint32_t bf2(bf16 a, bf16 b) {
    __nv_bfloat162 t; t.x = a; t.y = b;
    return *(uint32_t*)&t;
}
__device__ __forceinline__ uint32_t sw128(uint32_t o) { return o ^ ((o >> 3) & 0x70); }
__device__ __forceinline__ uint32_t sw64(uint32_t o)  { return o ^ ((o >> 3) & 0x30); }

// ============================ mma.sync GEMM v2 ============================
// C[M,1024] = A[M,1024] @ W. 3-term bf16 split. CTA tile 128x256, BK=32,
// 8 warps (2m x 4n), warp tile 64x64 -> 16 ldsm4 / 96 MMA per k16.
// SW64-swizzled smem (64B rows), 2-stage cp.async. 1 CTA/SM.
#define GBK 32
#define GNCHUNK (D_MODEL / GBK) /* 32 */
#define GA_TILE 8192            /* 128 x 64B */
#define GB_TILE 16384           /* 256 x 64B */
#define GSTAGE (2 * GA_TILE + 2 * GB_TILE) /* 49152 */
#define GEMM_SMEM (2 * GSTAGE)  /* 98304 */

__global__ __launch_bounds__(256) void gemm_mma(
    const bf16* __restrict__ Ah, const bf16* __restrict__ Al,
    const bf16* __restrict__ BhAll, const bf16* __restrict__ BlAll,
    float* __restrict__ Cf, bf16* __restrict__ ChAll, bf16* __restrict__ ClAll,
    float scale0)
{
    extern __shared__ char smem[];
    const uint32_t sb = smem_u32(smem);
    const int tid = threadIdx.x;
    const int wid = tid >> 5, lane = tid & 31;
    const int wm = wid & 1, wn = wid >> 1;  // 2m x 4n
    const int rowBase = blockIdx.y * 128;
    const int colBase = blockIdx.x * 256;

    const bf16* Bh = BhAll + (size_t)blockIdx.z * WSZ;
    const bf16* Bl = BlAll + (size_t)blockIdx.z * WSZ;

    const bf16* srcAh = Ah + (size_t)rowBase * D_MODEL;
    const bf16* srcAl = Al + (size_t)rowBase * D_MODEL;
    const bf16* srcBh = Bh + (size_t)colBase * D_MODEL;
    const bf16* srcBl = Bl + (size_t)colBase * D_MODEL;

    float acc[4][8][4];
#pragma unroll
    for (int mi = 0; mi < 4; mi++)
#pragma unroll
        for (int ni = 0; ni < 8; ni++)
#pragma unroll
            for (int j = 0; j < 4; j++) acc[mi][ni][j] = 0.f;

    auto load_chunk = [&](int c, int s) {
        const uint32_t tb = sb + s * GSTAGE;
        const int kofs = c * GBK;
#pragma unroll
        for (int i = 0; i < 2; i++) {  // A: 512 cp16 per array
            int f = i * 256 + tid;
            int row = f >> 2, cc = f & 3;
            uint32_t so = sw64((uint32_t)(row * 64 + cc * 16));
            cp16(tb + so, srcAh + (size_t)row * D_MODEL + kofs + cc * 8);
            cp16(tb + GA_TILE + so, srcAl + (size_t)row * D_MODEL + kofs + cc * 8);
        }
#pragma unroll
        for (int i = 0; i < 4; i++) {  // B: 1024 cp16 per array
            int f = i * 256 + tid;
            int row = f >> 2, cc = f & 3;
            uint32_t so = sw64((uint32_t)(row * 64 + cc * 16));
            cp16(tb + 2 * GA_TILE + so, srcBh + (size_t)row * D_MODEL + kofs + cc * 8);
            cp16(tb + 2 * GA_TILE + GB_TILE + so,
                 srcBl + (size_t)row * D_MODEL + kofs + cc * 8);
        }
    };

    const uint32_t lrow = lane & 15, lcol = lane >> 4;

    load_chunk(0, 0);
    cp_commit();

    for (int c = 0; c < GNCHUNK; c++) {
        if (c + 1 < GNCHUNK) {
            load_chunk(c + 1, (c + 1) & 1);
            cp_commit();
            cp_wait<1>();
        } else {
            cp_wait<0>();
        }
        __syncthreads();

        const uint32_t tb = sb + (c & 1) * GSTAGE;
        const uint32_t aTh = tb, aTl = tb + GA_TILE;
        const uint32_t bTh = tb + 2 * GA_TILE, bTl = tb + 2 * GA_TILE + GB_TILE;

#pragma unroll
        for (int k16 = 0; k16 < 2; k16++) {
            uint32_t a_h[4][4], a_l[4][4], bh[4][4], bl[4][4];
#pragma unroll
            for (int mi = 0; mi < 4; mi++) {
                uint32_t o = (uint32_t)((wm * 64 + mi * 16 + lrow) * 64 + k16 * 32 + lcol * 16);
                ldsm4(a_h[mi], aTh + sw64(o));
                ldsm4(a_l[mi], aTl + sw64(o));
            }
#pragma unroll
            for (int nb = 0; nb < 4; nb++) {
                uint32_t o = (uint32_t)((wn * 64 + nb * 16 + lrow) * 64 + k16 * 32 + lcol * 16);
                ldsm4(bh[nb], bTh + sw64(o));
                ldsm4(bl[nb], bTl + sw64(o));
            }
            // pass 1: Ah x Bh
#pragma unroll
            for (int mi = 0; mi < 4; mi++)
#pragma unroll
                for (int nb = 0; nb < 4; nb++) {
                    mma16816(acc[mi][2 * nb], a_h[mi], bh[nb][0], bh[nb][2]);
                    mma16816(acc[mi][2 * nb + 1], a_h[mi], bh[nb][1], bh[nb][3]);
                }
            // pass 2: Al x Bh
#pragma unroll
            for (int mi = 0; mi < 4; mi++)
#pragma unroll
                for (int nb = 0; nb < 4; nb++) {
                    mma16816(acc[mi][2 * nb], a_l[mi], bh[nb][0], bh[nb][2]);
                    mma16816(acc[mi][2 * nb + 1], a_l[mi], bh[nb][1], bh[nb][3]);
                }
            // pass 3: Ah x Bl
#pragma unroll
            for (int mi = 0; mi < 4; mi++)
#pragma unroll
                for (int nb = 0; nb < 4; nb++) {
                    mma16816(acc[mi][2 * nb], a_h[mi], bl[nb][0], bl[nb][2]);
                    mma16816(acc[mi][2 * nb + 1], a_h[mi], bl[nb][1], bl[nb][3]);
                }
        }
        __syncthreads();
    }

    // Epilogue
    const int g = lane >> 2, t4 = lane & 3;
    if (ChAll) {
        bf16* Ch = ChAll + (size_t)blockIdx.z * MTOT * D_MODEL;
        bf16* Cl = ClAll + (size_t)blockIdx.z * MTOT * D_MODEL;
        const float sc = (blockIdx.z == 0) ? scale0 : 1.0f;
#pragma unroll
        for (int mi = 0; mi < 4; mi++)
#pragma unroll
            for (int ni = 0; ni < 8; ni++) {
                int r = rowBase + wm * 64 + mi * 16 + g;
                int col = colBase + wn * 64 + ni * 8 + t4 * 2;
#pragma unroll
                for (int half = 0; half < 2; half++) {
                    float v0 = acc[mi][ni][2 * half] * sc;
                    float v1 = acc[mi][ni][2 * half + 1] * sc;
                    bf16 h0 = __float2bfloat16(v0);
                    bf16 h1 = __float2bfloat16(v1);
                    bf16 l0 = __float2bfloat16(v0 - __bfloat162float(h0));
                    bf16 l1 = __float2bfloat16(v1 - __bfloat162float(h1));
                    size_t o = (size_t)(r + 8 * half) * D_MODEL + col;
                    *(uint32_t*)&Ch[o] = bf2(h0, h1);
                    *(uint32_t*)&Cl[o] = bf2(l0, l1);
                }
            }
    } else {
#pragma unroll
        for (int mi = 0; mi < 4; mi++)
#pragma unroll
            for (int ni = 0; ni < 8; ni++) {
                int r = rowBase + wm * 64 + mi * 16 + g;
                int col = colBase + wn * 64 + ni * 8 + t4 * 2;
                *(float2*)&Cf[(size_t)r * D_MODEL + col] =
                    make_float2(acc[mi][ni][0], acc[mi][ni][1]);
                *(float2*)&Cf[(size_t)(r + 8) * D_MODEL + col] =
                    make_float2(acc[mi][ni][2], acc[mi][ni][3]);
            }
    }
}

// ==================== conversion kernels ====================
__global__ __launch_bounds__(256) void split_kernel(
    const float* __restrict__ in, bf16* __restrict__ hi, bf16* __restrict__ lo, int n2)
{
    int i = blockIdx.x * blockDim.x + threadIdx.x;
    if (i >= n2) return;
    float2 v = ((const float2*)in)[i];
    bf16 h0 = __float2bfloat16(v.x);
    bf16 l0 = __float2bfloat16(v.x - __bfloat162float(h0));
    bf16 h1 = __float2bfloat16(v.y);
    bf16 l1 = __float2bfloat16(v.y - __bfloat162float(h1));
    ((uint32_t*)hi)[i] = bf2(h0, h1);
    ((uint32_t*)lo)[i] = bf2(l0, l1);
}

__global__ __launch_bounds__(256) void wT_split3(
    const float* __restrict__ W0, const float* __restrict__ W1,
    const float* __restrict__ W2, bf16* __restrict__ Th, bf16* __restrict__ Tl)
{
    const float* W = (blockIdx.z == 0) ? W0 : (blockIdx.z == 1) ? W1 : W2;
    Th += (size_t)blockIdx.z * WSZ;
    Tl += (size_t)blockIdx.z * WSZ;
    __shared__ float t[32][33];
    int nx = blockIdx.x * 32 + threadIdx.x;
#pragma unroll
    for (int j = 0; j < 32; j += 8)
        t[threadIdx.y + j][threadIdx.x] =
            W[(size_t)(blockIdx.y * 32 + threadIdx.y + j) * D_MODEL + nx];
    __syncthreads();
    int k = blockIdx.y * 32 + threadIdx.x;
#pragma unroll
    for (int j = 0; j < 32; j += 8) {
        int n = blockIdx.x * 32 + threadIdx.y + j;
        float v = t[threadIdx.x][threadIdx.y + j];
        bf16 h = __float2bfloat16(v);
        bf16 l = __float2bfloat16(v - __bfloat162float(h));
        Th[(size_t)n * D_MODEL + k] = h;
        Tl[(size_t)n * D_MODEL + k] = l;
    }
}

// ==================== tensor-core flash attention v4 ====================
// CTA: 128 threads (4 warps), 64 queries, one (b,h). Swizzled smem (no pad)
// -> 64KB/CTA -> 3 CTAs/SM. kv tile processed as two 64-kv halves to keep
// registers under the 170 cap. Phase-pipelined single-buffer K/V loads.
#define KROW 128
#define KTILE (128 * KROW)          /* 16384 */
#define ATTN_SMEM (4 * KTILE)       /* 65536: Kh,Kl,Vh,Vl */

__global__ __launch_bounds__(128, 3) void attn_mma(
    const bf16* __restrict__ Qh, const bf16* __restrict__ Ql,
    const bf16* __restrict__ Kh, const bf16* __restrict__ Kl,
    const bf16* __restrict__ Vh, const bf16* __restrict__ Vl,
    bf16* __restrict__ MH, bf16* __restrict__ ML)
{
    extern __shared__ char smraw[];
    const uint32_t sb = smem_u32(smraw);
    const int tid = threadIdx.x;
    const int wid = tid >> 5, lane = tid & 31;
    const uint32_t lrow = lane & 15, lcol = lane >> 4;
    const int g = lane >> 2, t4 = lane & 3;

    const int q0 = blockIdx.x * 64;
    const int h = blockIdx.y;
    const int b = blockIdx.z;
    const size_t qrow = (size_t)b * SEQ + q0;
    const size_t krow0 = (size_t)b * SEQ;
    const int hofs = h * HEAD_DIM;

    const uint32_t skh = sb, skl = sb + KTILE;
    const uint32_t svh = sb + 2 * KTILE, svl = sb + 3 * KTILE;

    auto load_k = [&](int t) {
        const size_t kr = krow0 + (size_t)t * 128;
#pragma unroll
        for (int i = 0; i < 16; i++) {
            int f = i * 128 + tid;
            int arr = f >> 10;
            int r = (f >> 3) & 127, cg = f & 7;
            const bf16* p = arr ? Kl : Kh;
            cp16(sb + arr * KTILE + sw128((uint32_t)(r * KROW + cg * 16)),
                 p + (kr + r) * D_MODEL + hofs + cg * 8);
        }
    };
    auto load_v = [&](int t) {
        const size_t kr = krow0 + (size_t)t * 128;
#pragma unroll
        for (int i = 0; i < 16; i++) {
            int f = i * 128 + tid;
            int arr = f >> 10;
            int r = (f >> 3) & 127, cg = f & 7;
            const bf16* p = arr ? Vl : Vh;
            cp16(sb + (2 + arr) * KTILE + sw128((uint32_t)(r * KROW + cg * 16)),
                 p + (kr + r) * D_MODEL + hofs + cg * 8);
        }
    };

    load_k(0); cp_commit();
    load_v(0); cp_commit();

    // ---- Q fragments direct from gmem ----
    uint32_t qhf[4][4], qlf[4][4];
    {
        const size_t r0 = qrow + wid * 16 + g;
        const int c0 = hofs + t4 * 2;
#pragma unroll
        for (int kc = 0; kc < 4; kc++) {
#pragma unroll
            for (int q = 0; q < 4; q++) {
                size_t r = r0 + ((q & 1) ? 8 : 0);
                int c = c0 + kc * 16 + ((q & 2) ? 8 : 0);
                qhf[kc][q] = *(const uint32_t*)&Qh[r * D_MODEL + c];
                qlf[kc][q] = *(const uint32_t*)&Ql[r * D_MODEL + c];
            }
        }
    }

    float o[8][4];
#pragma unroll
    for (int di = 0; di < 8; di++)
#pragma unroll
        for (int j = 0; j < 4; j++) o[di][j] = 0.f;
    float m_prev[2] = {-1e30f, -1e30f};
    float lsum[2] = {0.f, 0.f};

    const int NT = SEQ / 128;  // 16

    for (int t = 0; t < NT; t++) {
        cp_wait<1>();       // K_t landed
        __syncthreads();

#pragma unroll
        for (int hf = 0; hf < 2; hf++) {
            const int rbase = hf * 64;
            // ---- S(half) = Q K^T (3-term) ----
            float s[8][4];
#pragma unroll
            for (int ni = 0; ni < 8; ni++)
#pragma unroll
                for (int j = 0; j < 4; j++) s[ni][j] = 0.f;

#pragma unroll
            for (int kc = 0; kc < 4; kc++) {
                uint32_t kf[4][4];
#pragma unroll
                for (int np = 0; np < 4; np++)
                    ldsm4(kf[np], skh + sw128((uint32_t)((rbase + np * 16 + lrow) * KROW +
                                                         kc * 32 + lcol * 16)));
#pragma unroll
                for (int ni = 0; ni < 8; ni++) {
                    int np = ni >> 1, hl = ni & 1;
                    mma16816(s[ni], qhf[kc], kf[np][hl], kf[np][hl + 2]);
                }
#pragma unroll
                for (int ni = 0; ni < 8; ni++) {
                    int np = ni >> 1, hl = ni & 1;
                    mma16816(s[ni], qlf[kc], kf[np][hl], kf[np][hl + 2]);
                }
            }
#pragma unroll
            for (int kc = 0; kc < 4; kc++) {
                uint32_t kf[4][4];
#pragma unroll
                for (int np = 0; np < 4; np++)
                    ldsm4(kf[np], skl + sw128((uint32_t)((rbase + np * 16 + lrow) * KROW +
                                                         kc * 32 + lcol * 16)));
#pragma unroll
                for (int ni = 0; ni < 8; ni++) {
                    int np = ni >> 1, hl = ni & 1;
                    mma16816(s[ni], qhf[kc], kf[np][hl], kf[np][hl + 2]);
                }
            }

            if (hf == 1) {  // all warps done with K_t -> prefetch K_{t+1}
                __syncthreads();
                if (t + 1 < NT) { load_k(t + 1); cp_commit(); }
            }

            // ---- online softmax on this half ----
#pragma unroll
            for (int rg = 0; rg < 2; rg++) {
                float mx = -1e30f;
#pragma unroll
                for (int ni = 0; ni < 8; ni++)
                    mx = fmaxf(mx, fmaxf(s[ni][2 * rg], s[ni][2 * rg + 1]));
                mx = fmaxf(mx, __shfl_xor_sync(0xffffffffu, mx, 1));
                mx = fmaxf(mx, __shfl_xor_sync(0xffffffffu, mx, 2));
                float mn = fmaxf(m_prev[rg], mx);
                float al = __expf(m_prev[rg] - mn);
                float sum = 0.f;
#pragma unroll
                for (int ni = 0; ni < 8; ni++) {
                    float p0 = __expf(s[ni][2 * rg] - mn);
                    float p1 = __expf(s[ni][2 * rg + 1] - mn);
                    s[ni][2 * rg] = p0;
                    s[ni][2 * rg + 1] = p1;
                    sum += p0 + p1;
                }
                sum += __shfl_xor_sync(0xffffffffu, sum, 1);
                sum += __shfl_xor_sync(0xffffffffu, sum, 2);
                lsum[rg] = lsum[rg] * al + sum;
                m_prev[rg] = mn;
#pragma unroll
                for (int di = 0; di < 8; di++) {
                    o[di][2 * rg] *= al;
                    o[di][2 * rg + 1] *= al;
                }
            }

            if (hf == 0) {  // V_t must be resident before first PV
                cp_wait<0>();
                __syncthreads();
            }

            // ---- O += P V (half, 3-term) ----
#pragma unroll
            for (int kc2 = 0; kc2 < 4; kc2++) {
                int j0 = 2 * kc2, j1 = j0 + 1;
                uint32_t ah[4], al4[4];
#pragma unroll
                for (int q = 0; q < 4; q++) {
                    const float* sp = (q & 2) ? s[j1] : s[j0];
                    float v0 = sp[(q & 1) * 2], v1 = sp[(q & 1) * 2 + 1];
                    bf16 h0 = __float2bfloat16(v0);
                    bf16 h1 = __float2bfloat16(v1);
                    ah[q] = bf2(h0, h1);
                    al4[q] = bf2(__float2bfloat16(v0 - __bfloat162float(h0)),
                                 __float2bfloat16(v1 - __bfloat162float(h1)));
                }
                uint32_t vhf[4][4], vlf[4][4];
#pragma unroll
                for (int dp = 0; dp < 4; dp++) {
                    uint32_t a = sw128((uint32_t)((rbase + kc2 * 16 + lrow) * KROW +
                                                  dp * 32 + lcol * 16));
                    ldsm4t(vhf[dp], svh + a);
                    ldsm4t(vlf[dp], svl + a);
                }
#pragma unroll
                for (int di = 0; di < 8; di++) {
                    int dp = di >> 1, off = (di & 1) * 2;
                    mma16816(o[di], ah, vhf[dp][off], vhf[dp][off + 1]);
                }
#pragma unroll
                for (int di = 0; di < 8; di++) {
                    int dp = di >> 1, off = (di & 1) * 2;
                    mma16816(o[di], ah, vlf[dp][off], vlf[dp][off + 1]);
                }
#pragma unroll
                for (int di = 0; di < 8; di++) {
                    int dp = di >> 1, off = (di & 1) * 2;
                    mma16816(o[di], al4, vhf[dp][off], vhf[dp][off + 1]);
                }
            }
        }

        __syncthreads();   // all warps done with V_t
        if (t + 1 < NT) { load_v(t + 1); cp_commit(); }
    }

    // ---- epilogue ----
    float inv_l[2] = {1.f / lsum[0], 1.f / lsum[1]};
#pragma unroll
    for (int di = 0; di < 8; di++) {
#pragma unroll
        for (int rg = 0; rg < 2; rg++) {
            float v0 = o[di][2 * rg] * inv_l[rg];
            float v1 = o[di][2 * rg + 1] * inv_l[rg];
            bf16 h0 = __float2bfloat16(v0);
            bf16 h1 = __float2bfloat16(v1);
            size_t idx = (qrow + wid * 16 + g + 8 * rg) * D_MODEL + hofs + di * 8 + t4 * 2;
            *(uint32_t*)&MH[idx] = bf2(h0, h1);
            *(uint32_t*)&ML[idx] = bf2(__float2bfloat16(v0 - __bfloat162float(h0)),
                                       __float2bfloat16(v1 - __bfloat162float(h1)));
        }
    }
}

// ---------------------------------------------------------------------------
extern "C" void kernel_launch(void* const* d_in, const int* in_sizes, int n_in,
                              void* d_out, int out_size)
{
    (void)in_sizes; (void)n_in; (void)out_size;
    const float* x    = (const float*)d_in[0];
    const float* W_q  = (const float*)d_in[1];
    const float* W_k  = (const float*)d_in[2];
    const float* W_v  = (const float*)d_in[3];
    const float* fc_o = (const float*)d_in[4];
    float* out = (float*)d_out;

    bf16 *xh, *xl, *qkvh, *qkvl, *mh, *ml, *wh, *wl;
    cudaGetSymbolAddress((void**)&xh, g_xh);
    cudaGetSymbolAddress((void**)&xl, g_xl);
    cudaGetSymbolAddress((void**)&qkvh, g_qkvh);
    cudaGetSymbolAddress((void**)&qkvl, g_qkvl);
    cudaGetSymbolAddress((void**)&mh, g_mh);
    cudaGetSymbolAddress((void**)&ml, g_ml);
    cudaGetSymbolAddress((void**)&wh, g_wh);
    cudaGetSymbolAddress((void**)&wl, g_wl);

    cudaFuncSetAttribute(gemm_mma, cudaFuncAttributeMaxDynamicSharedMemorySize, GEMM_SMEM);
    cudaFuncSetAttribute(attn_mma, cudaFuncAttributeMaxDynamicSharedMemorySize, ATTN_SMEM);

    const int n2_x = MTOT * D_MODEL / 2;
    dim3 wgrid(D_MODEL / 32, D_MODEL / 32, 3);
    dim3 wblk(32, 8);

    split_kernel<<<(n2_x + 255) / 256, 256>>>(x, xh, xl, n2_x);
    wT_split3<<<wgrid, wblk>>>(W_q, W_k, W_v, wh, wl);

    // QKV: split bf16 outputs, Q pre-scaled by 1/sqrt(Hd)
    dim3 ggrid3(D_MODEL / 256, MTOT / 128, 3);  // (4, 64, 3)
    gemm_mma<<<ggrid3, 256, GEMM_SMEM>>>(xh, xl, wh, wl, nullptr, qkvh, qkvl, 0.125f);

    const size_t PL = (size_t)MTOT * D_MODEL;
    dim3 attn_grid(SEQ / 64, HEADS, BATCH);  // (32, 16, 4)
    attn_mma<<<attn_grid, 128, ATTN_SMEM>>>(qkvh, qkvl, qkvh + PL, qkvl + PL,
                                            qkvh + 2 * PL, qkvl + 2 * PL, mh, ml);

    dim3 wgrid1(D_MODEL / 32, D_MODEL / 32, 1);
    wT_split3<<<wgrid1, wblk>>>(fc_o, fc_o, fc_o, wh, wl);
    dim3 ggrid1(D_MODEL / 256, MTOT / 128, 1);  // (4, 64, 1)
    gemm_mma<<<ggrid1, 256, GEMM_SMEM>>>(mh, ml, wh, wl, out, nullptr, nullptr, 1.0f);
}

// round 9
// speedup vs baseline: 1.1324x; 1.1183x over previous
#include <cuda_runtime.h>
#include <cuda_bf16.h>
#include <math.h>
#include <stdint.h>

#define D_MODEL 1024
#define HEADS 16
#define HEAD_DIM 64
#define BATCH 4
#define SEQ 2048
#define MTOT (BATCH * SEQ) /* 8192 */
#define WSZ (D_MODEL * D_MODEL)

typedef __nv_bfloat16 bf16;

// ---- scratch (static __device__; allocation APIs forbidden) ----
__device__ bf16 g_xh[(size_t)MTOT * D_MODEL];
__device__ bf16 g_xl[(size_t)MTOT * D_MODEL];
__device__ bf16 g_qkvh[(size_t)3 * MTOT * D_MODEL];
__device__ bf16 g_qkvl[(size_t)3 * MTOT * D_MODEL];
__device__ bf16 g_mh[(size_t)MTOT * D_MODEL];
__device__ bf16 g_ml[(size_t)MTOT * D_MODEL];
__device__ bf16 g_wh[(size_t)4 * WSZ];
__device__ bf16 g_wl[(size_t)4 * WSZ];

// ============================ PTX helpers ============================
__device__ __forceinline__ uint32_t smem_u32(const void* p) {
    uint32_t a;
    asm("{ .reg .u64 t; cvta.to.shared.u64 t, %1; cvt.u32.u64 %0, t; }"
        : "=r"(a) : "l"(p));
    return a;
}
__device__ __forceinline__ void cp16(uint32_t s, const void* g) {
    asm volatile("cp.async.cg.shared.global [%0], [%1], 16;" :: "r"(s), "l"(g) : "memory");
}
__device__ __forceinline__ void cp_commit() {
    asm volatile("cp.async.commit_group;" ::: "memory");
}
template <int N> __device__ __forceinline__ void cp_wait() {
    asm volatile("cp.async.wait_group %0;" :: "n"(N) : "memory");
}
__device__ __forceinline__ void ldsm4(uint32_t* r, uint32_t addr) {
    asm volatile("ldmatrix.sync.aligned.m8n8.x4.shared.b16 {%0,%1,%2,%3}, [%4];"
                 : "=r"(r[0]), "=r"(r[1]), "=r"(r[2]), "=r"(r[3]) : "r"(addr));
}
__device__ __forceinline__ void ldsm4t(uint32_t* r, uint32_t addr) {
    asm volatile("ldmatrix.sync.aligned.m8n8.x4.trans.shared.b16 {%0,%1,%2,%3}, [%4];"
                 : "=r"(r[0]), "=r"(r[1]), "=r"(r[2]), "=r"(r[3]) : "r"(addr));
}
__device__ __forceinline__ void mma16816(float* c, const uint32_t* a,
                                         uint32_t b0, uint32_t b1) {
    asm volatile(
        "mma.sync.aligned.m16n8k16.row.col.f32.bf16.bf16.f32 "
        "{%0,%1,%2,%3},{%4,%5,%6,%7},{%8,%9},{%0,%1,%2,%3};"
        : "+f"(c[0]), "+f"(c[1]), "+f"(c[2]), "+f"(c[3])
        : "r"(a[0]), "r"(a[1]), "r"(a[2]), "r"(a[3]), "r"(b0), "r"(b1));
}
__device__ __forceinline__ uint32_t bf2(bf16 a, bf16 b) {
    __nv_bfloat162 t; t.x = a; t.y = b;
    return *(uint32_t*)&t;
}
__device__ __forceinline__ uint32_t sw128(uint32_t o) { return o ^ ((o >> 3) & 0x70); }
__device__ __forceinline__ uint32_t sw64(uint32_t o)  { return o ^ ((o >> 3) & 0x30); }

// ============================ mma.sync GEMM v3 ============================
// C[M,1024] = A[M,1024] @ W. 3-term bf16 split. CTA tile 128x128, BK=32,
// 8 warps (4m x 2n), warp tile 32x64. SW64 smem rows (64B, no pad),
// 3-stage cp.async pipeline, 2 CTAs/SM (16 warps).
#define GBK 32
#define GNCHUNK (D_MODEL / GBK) /* 32 */
#define GARR 8192               /* one 128x64B array */
#define GST (4 * GARR)          /* stage: Ah,Al,Bh,Bl = 32KB */
#define GEMM_SMEM (3 * GST)     /* 98304 */

__global__ __launch_bounds__(256, 2) void gemm_mma(
    const bf16* __restrict__ Ah, const bf16* __restrict__ Al,
    const bf16* __restrict__ BhAll, const bf16* __restrict__ BlAll,
    float* __restrict__ Cf, bf16* __restrict__ ChAll, bf16* __restrict__ ClAll,
    float scale0)
{
    extern __shared__ char smem[];
    const uint32_t sb = smem_u32(smem);
    const int tid = threadIdx.x;
    const int wid = tid >> 5, lane = tid & 31;
    const int wm = wid & 3, wn = wid >> 2;  // 4m x 2n, warp tile 32x64
    const int rowBase = blockIdx.y * 128;
    const int colBase = blockIdx.x * 128;

    const bf16* Bh = BhAll + (size_t)blockIdx.z * WSZ;
    const bf16* Bl = BlAll + (size_t)blockIdx.z * WSZ;

    const bf16* srcAh = Ah + (size_t)rowBase * D_MODEL;
    const bf16* srcAl = Al + (size_t)rowBase * D_MODEL;
    const bf16* srcBh = Bh + (size_t)colBase * D_MODEL;
    const bf16* srcBl = Bl + (size_t)colBase * D_MODEL;

    float acc[2][8][4];
#pragma unroll
    for (int mi = 0; mi < 2; mi++)
#pragma unroll
        for (int ni = 0; ni < 8; ni++)
#pragma unroll
            for (int j = 0; j < 4; j++) acc[mi][ni][j] = 0.f;

    auto load_chunk = [&](int c, int stg) {
        const uint32_t tb = sb + stg * GST;
        const int kofs = c * GBK;
#pragma unroll
        for (int i = 0; i < 2; i++) {
            int f = i * 256 + tid;      // 0..511
            int row = f >> 2, cc = f & 3;
            uint32_t so = sw64((uint32_t)(row * 64 + cc * 16));
            const size_t go = (size_t)row * D_MODEL + kofs + cc * 8;
            cp16(tb + so, srcAh + go);
            cp16(tb + GARR + so, srcAl + go);
            cp16(tb + 2 * GARR + so, srcBh + go);
            cp16(tb + 3 * GARR + so, srcBl + go);
        }
    };

    const uint32_t lrow = lane & 15, lcol = lane >> 4;

    load_chunk(0, 0); cp_commit();
    load_chunk(1, 1); cp_commit();

    for (int c = 0; c < GNCHUNK; c++) {
        if (c + 1 < GNCHUNK) cp_wait<1>(); else cp_wait<0>();
        __syncthreads();
        if (c + 2 < GNCHUNK) { load_chunk(c + 2, (c + 2) % 3); cp_commit(); }

        const uint32_t tb = sb + (c % 3) * GST;
#pragma unroll
        for (int k16 = 0; k16 < 2; k16++) {
            const uint32_t kb = k16 * 32;
            uint32_t a_h[2][4], a_l[2][4], bfr[4][4];
#pragma unroll
            for (int mi = 0; mi < 2; mi++) {
                uint32_t o = (uint32_t)((wm * 32 + mi * 16 + lrow) * 64 + kb + lcol * 16);
                ldsm4(a_h[mi], tb + sw64(o));
                ldsm4(a_l[mi], tb + GARR + sw64(o));
            }
#pragma unroll
            for (int nb = 0; nb < 4; nb++) {
                uint32_t o = (uint32_t)((wn * 64 + nb * 16 + lrow) * 64 + kb + lcol * 16);
                ldsm4(bfr[nb], tb + 2 * GARR + sw64(o));
            }
            // pass 1: Ah x Bh
#pragma unroll
            for (int nb = 0; nb < 4; nb++)
#pragma unroll
                for (int mi = 0; mi < 2; mi++) {
                    mma16816(acc[mi][2 * nb], a_h[mi], bfr[nb][0], bfr[nb][2]);
                    mma16816(acc[mi][2 * nb + 1], a_h[mi], bfr[nb][1], bfr[nb][3]);
                }
            // pass 2: Al x Bh
#pragma unroll
            for (int nb = 0; nb < 4; nb++)
#pragma unroll
                for (int mi = 0; mi < 2; mi++) {
                    mma16816(acc[mi][2 * nb], a_l[mi], bfr[nb][0], bfr[nb][2]);
                    mma16816(acc[mi][2 * nb + 1], a_l[mi], bfr[nb][1], bfr[nb][3]);
                }
            // pass 3: Ah x Bl (reuse bfr registers)
#pragma unroll
            for (int nb = 0; nb < 4; nb++) {
                uint32_t o = (uint32_t)((wn * 64 + nb * 16 + lrow) * 64 + kb + lcol * 16);
                ldsm4(bfr[nb], tb + 3 * GARR + sw64(o));
            }
#pragma unroll
            for (int nb = 0; nb < 4; nb++)
#pragma unroll
                for (int mi = 0; mi < 2; mi++) {
                    mma16816(acc[mi][2 * nb], a_h[mi], bfr[nb][0], bfr[nb][2]);
                    mma16816(acc[mi][2 * nb + 1], a_h[mi], bfr[nb][1], bfr[nb][3]);
                }
        }
    }

    __syncthreads();

    // Epilogue
    const int g = lane >> 2, t4 = lane & 3;
    if (ChAll) {
        bf16* Ch = ChAll + (size_t)blockIdx.z * MTOT * D_MODEL;
        bf16* Cl = ClAll + (size_t)blockIdx.z * MTOT * D_MODEL;
        const float sc = (blockIdx.z == 0) ? scale0 : 1.0f;
#pragma unroll
        for (int mi = 0; mi < 2; mi++)
#pragma unroll
            for (int ni = 0; ni < 8; ni++) {
                int r = rowBase + wm * 32 + mi * 16 + g;
                int col = colBase + wn * 64 + ni * 8 + t4 * 2;
#pragma unroll
                for (int half = 0; half < 2; half++) {
                    float v0 = acc[mi][ni][2 * half] * sc;
                    float v1 = acc[mi][ni][2 * half + 1] * sc;
                    bf16 h0 = __float2bfloat16(v0);
                    bf16 h1 = __float2bfloat16(v1);
                    bf16 l0 = __float2bfloat16(v0 - __bfloat162float(h0));
                    bf16 l1 = __float2bfloat16(v1 - __bfloat162float(h1));
                    size_t o = (size_t)(r + 8 * half) * D_MODEL + col;
                    *(uint32_t*)&Ch[o] = bf2(h0, h1);
                    *(uint32_t*)&Cl[o] = bf2(l0, l1);
                }
            }
    } else {
#pragma unroll
        for (int mi = 0; mi < 2; mi++)
#pragma unroll
            for (int ni = 0; ni < 8; ni++) {
                int r = rowBase + wm * 32 + mi * 16 + g;
                int col = colBase + wn * 64 + ni * 8 + t4 * 2;
                *(float2*)&Cf[(size_t)r * D_MODEL + col] =
                    make_float2(acc[mi][ni][0], acc[mi][ni][1]);
                *(float2*)&Cf[(size_t)(r + 8) * D_MODEL + col] =
                    make_float2(acc[mi][ni][2], acc[mi][ni][3]);
            }
    }
}

// ==================== conversion kernels ====================
__global__ __launch_bounds__(256) void split_kernel(
    const float* __restrict__ in, bf16* __restrict__ hi, bf16* __restrict__ lo, int n2)
{
    int i = blockIdx.x * blockDim.x + threadIdx.x;
    if (i >= n2) return;
    float2 v = ((const float2*)in)[i];
    bf16 h0 = __float2bfloat16(v.x);
    bf16 l0 = __float2bfloat16(v.x - __bfloat162float(h0));
    bf16 h1 = __float2bfloat16(v.y);
    bf16 l1 = __float2bfloat16(v.y - __bfloat162float(h1));
    ((uint32_t*)hi)[i] = bf2(h0, h1);
    ((uint32_t*)lo)[i] = bf2(l0, l1);
}

// W [K][N] fp32 -> Wt hi/lo [N][K] bf16 (transpose + split), 4 weights via z
__global__ __launch_bounds__(256) void wT_split4(
    const float* __restrict__ W0, const float* __restrict__ W1,
    const float* __restrict__ W2, const float* __restrict__ W3,
    bf16* __restrict__ Th, bf16* __restrict__ Tl)
{
    const float* W = (blockIdx.z == 0) ? W0 : (blockIdx.z == 1) ? W1
                     : (blockIdx.z == 2) ? W2 : W3;
    Th += (size_t)blockIdx.z * WSZ;
    Tl += (size_t)blockIdx.z * WSZ;
    __shared__ float t[32][33];
    int nx = blockIdx.x * 32 + threadIdx.x;
#pragma unroll
    for (int j = 0; j < 32; j += 8)
        t[threadIdx.y + j][threadIdx.x] =
            W[(size_t)(blockIdx.y * 32 + threadIdx.y + j) * D_MODEL + nx];
    __syncthreads();
    int k = blockIdx.y * 32 + threadIdx.x;
#pragma unroll
    for (int j = 0; j < 32; j += 8) {
        int n = blockIdx.x * 32 + threadIdx.y + j;
        float v = t[threadIdx.x][threadIdx.y + j];
        bf16 h = __float2bfloat16(v);
        bf16 l = __float2bfloat16(v - __bfloat162float(h));
        Th[(size_t)n * D_MODEL + k] = h;
        Tl[(size_t)n * D_MODEL + k] = l;
    }
}

// ==================== tensor-core flash attention v4 (unchanged) ====================
#define KROW 128
#define KTILE (128 * KROW)          /* 16384 */
#define ATTN_SMEM (4 * KTILE)       /* 65536: Kh,Kl,Vh,Vl */

__global__ __launch_bounds__(128, 3) void attn_mma(
    const bf16* __restrict__ Qh, const bf16* __restrict__ Ql,
    const bf16* __restrict__ Kh, const bf16* __restrict__ Kl,
    const bf16* __restrict__ Vh, const bf16* __restrict__ Vl,
    bf16* __restrict__ MH, bf16* __restrict__ ML)
{
    extern __shared__ char smraw[];
    const uint32_t sb = smem_u32(smraw);
    const int tid = threadIdx.x;
    const int wid = tid >> 5, lane = tid & 31;
    const uint32_t lrow = lane & 15, lcol = lane >> 4;
    const int g = lane >> 2, t4 = lane & 3;

    const int q0 = blockIdx.x * 64;
    const int h = blockIdx.y;
    const int b = blockIdx.z;
    const size_t qrow = (size_t)b * SEQ + q0;
    const size_t krow0 = (size_t)b * SEQ;
    const int hofs = h * HEAD_DIM;

    const uint32_t skh = sb, skl = sb + KTILE;
    const uint32_t svh = sb + 2 * KTILE, svl = sb + 3 * KTILE;

    auto load_k = [&](int t) {
        const size_t kr = krow0 + (size_t)t * 128;
#pragma unroll
        for (int i = 0; i < 16; i++) {
            int f = i * 128 + tid;
            int arr = f >> 10;
            int r = (f >> 3) & 127, cg = f & 7;
            const bf16* p = arr ? Kl : Kh;
            cp16(sb + arr * KTILE + sw128((uint32_t)(r * KROW + cg * 16)),
                 p + (kr + r) * D_MODEL + hofs + cg * 8);
        }
    };
    auto load_v = [&](int t) {
        const size_t kr = krow0 + (size_t)t * 128;
#pragma unroll
        for (int i = 0; i < 16; i++) {
            int f = i * 128 + tid;
            int arr = f >> 10;
            int r = (f >> 3) & 127, cg = f & 7;
            const bf16* p = arr ? Vl : Vh;
            cp16(sb + (2 + arr) * KTILE + sw128((uint32_t)(r * KROW + cg * 16)),
                 p + (kr + r) * D_MODEL + hofs + cg * 8);
        }
    };

    load_k(0); cp_commit();
    load_v(0); cp_commit();

    uint32_t qhf[4][4], qlf[4][4];
    {
        const size_t r0 = qrow + wid * 16 + g;
        const int c0 = hofs + t4 * 2;
#pragma unroll
        for (int kc = 0; kc < 4; kc++) {
#pragma unroll
            for (int q = 0; q < 4; q++) {
                size_t r = r0 + ((q & 1) ? 8 : 0);
                int c = c0 + kc * 16 + ((q & 2) ? 8 : 0);
                qhf[kc][q] = *(const uint32_t*)&Qh[r * D_MODEL + c];
                qlf[kc][q] = *(const uint32_t*)&Ql[r * D_MODEL + c];
            }
        }
    }

    float o[8][4];
#pragma unroll
    for (int di = 0; di < 8; di++)
#pragma unroll
        for (int j = 0; j < 4; j++) o[di][j] = 0.f;
    float m_prev[2] = {-1e30f, -1e30f};
    float lsum[2] = {0.f, 0.f};

    const int NT = SEQ / 128;

    for (int t = 0; t < NT; t++) {
        cp_wait<1>();
        __syncthreads();

#pragma unroll
        for (int hf = 0; hf < 2; hf++) {
            const int rbase = hf * 64;
            float s[8][4];
#pragma unroll
            for (int ni = 0; ni < 8; ni++)
#pragma unroll
                for (int j = 0; j < 4; j++) s[ni][j] = 0.f;

#pragma unroll
            for (int kc = 0; kc < 4; kc++) {
                uint32_t kf[4][4];
#pragma unroll
                for (int np = 0; np < 4; np++)
                    ldsm4(kf[np], skh + sw128((uint32_t)((rbase + np * 16 + lrow) * KROW +
                                                         kc * 32 + lcol * 16)));
#pragma unroll
                for (int ni = 0; ni < 8; ni++) {
                    int np = ni >> 1, hl = ni & 1;
                    mma16816(s[ni], qhf[kc], kf[np][hl], kf[np][hl + 2]);
                }
#pragma unroll
                for (int ni = 0; ni < 8; ni++) {
                    int np = ni >> 1, hl = ni & 1;
                    mma16816(s[ni], qlf[kc], kf[np][hl], kf[np][hl + 2]);
                }
            }
#pragma unroll
            for (int kc = 0; kc < 4; kc++) {
                uint32_t kf[4][4];
#pragma unroll
                for (int np = 0; np < 4; np++)
                    ldsm4(kf[np], skl + sw128((uint32_t)((rbase + np * 16 + lrow) * KROW +
                                                         kc * 32 + lcol * 16)));
#pragma unroll
                for (int ni = 0; ni < 8; ni++) {
                    int np = ni >> 1, hl = ni & 1;
                    mma16816(s[ni], qhf[kc], kf[np][hl], kf[np][hl + 2]);
                }
            }

            if (hf == 1) {
                __syncthreads();
                if (t + 1 < NT) { load_k(t + 1); cp_commit(); }
            }

#pragma unroll
            for (int rg = 0; rg < 2; rg++) {
                float mx = -1e30f;
#pragma unroll
                for (int ni = 0; ni < 8; ni++)
                    mx = fmaxf(mx, fmaxf(s[ni][2 * rg], s[ni][2 * rg + 1]));
                mx = fmaxf(mx, __shfl_xor_sync(0xffffffffu, mx, 1));
                mx = fmaxf(mx, __shfl_xor_sync(0xffffffffu, mx, 2));
                float mn = fmaxf(m_prev[rg], mx);
                float al = __expf(m_prev[rg] - mn);
                float sum = 0.f;
#pragma unroll
                for (int ni = 0; ni < 8; ni++) {
                    float p0 = __expf(s[ni][2 * rg] - mn);
                    float p1 = __expf(s[ni][2 * rg + 1] - mn);
                    s[ni][2 * rg] = p0;
                    s[ni][2 * rg + 1] = p1;
                    sum += p0 + p1;
                }
                sum += __shfl_xor_sync(0xffffffffu, sum, 1);
                sum += __shfl_xor_sync(0xffffffffu, sum, 2);
                lsum[rg] = lsum[rg] * al + sum;
                m_prev[rg] = mn;
#pragma unroll
                for (int di = 0; di < 8; di++) {
                    o[di][2 * rg] *= al;
                    o[di][2 * rg + 1] *= al;
                }
            }

            if (hf == 0) {
                cp_wait<0>();
                __syncthreads();
            }

#pragma unroll
            for (int kc2 = 0; kc2 < 4; kc2++) {
                int j0 = 2 * kc2, j1 = j0 + 1;
                uint32_t ah[4], al4[4];
#pragma unroll
                for (int q = 0; q < 4; q++) {
                    const float* sp = (q & 2) ? s[j1] : s[j0];
                    float v0 = sp[(q & 1) * 2], v1 = sp[(q & 1) * 2 + 1];
                    bf16 h0 = __float2bfloat16(v0);
                    bf16 h1 = __float2bfloat16(v1);
                    ah[q] = bf2(h0, h1);
                    al4[q] = bf2(__float2bfloat16(v0 - __bfloat162float(h0)),
                                 __float2bfloat16(v1 - __bfloat162float(h1)));
                }
                uint32_t vhf[4][4], vlf[4][4];
#pragma unroll
                for (int dp = 0; dp < 4; dp++) {
                    uint32_t a = sw128((uint32_t)((rbase + kc2 * 16 + lrow) * KROW +
                                                  dp * 32 + lcol * 16));
                    ldsm4t(vhf[dp], svh + a);
                    ldsm4t(vlf[dp], svl + a);
                }
#pragma unroll
                for (int di = 0; di < 8; di++) {
                    int dp = di >> 1, off = (di & 1) * 2;
                    mma16816(o[di], ah, vhf[dp][off], vhf[dp][off + 1]);
                }
#pragma unroll
                for (int di = 0; di < 8; di++) {
                    int dp = di >> 1, off = (di & 1) * 2;
                    mma16816(o[di], ah, vlf[dp][off], vlf[dp][off + 1]);
                }
#pragma unroll
                for (int di = 0; di < 8; di++) {
                    int dp = di >> 1, off = (di & 1) * 2;
                    mma16816(o[di], al4, vhf[dp][off], vhf[dp][off + 1]);
                }
            }
        }

        __syncthreads();
        if (t + 1 < NT) { load_v(t + 1); cp_commit(); }
    }

    float inv_l[2] = {1.f / lsum[0], 1.f / lsum[1]};
#pragma unroll
    for (int di = 0; di < 8; di++) {
#pragma unroll
        for (int rg = 0; rg < 2; rg++) {
            float v0 = o[di][2 * rg] * inv_l[rg];
            float v1 = o[di][2 * rg + 1] * inv_l[rg];
            bf16 h0 = __float2bfloat16(v0);
            bf16 h1 = __float2bfloat16(v1);
            size_t idx = (qrow + wid * 16 + g + 8 * rg) * D_MODEL + hofs + di * 8 + t4 * 2;
            *(uint32_t*)&MH[idx] = bf2(h0, h1);
            *(uint32_t*)&ML[idx] = bf2(__float2bfloat16(v0 - __bfloat162float(h0)),
                                       __float2bfloat16(v1 - __bfloat162float(h1)));
        }
    }
}

// ---------------------------------------------------------------------------
extern "C" void kernel_launch(void* const* d_in, const int* in_sizes, int n_in,
                              void* d_out, int out_size)
{
    (void)in_sizes; (void)n_in; (void)out_size;
    const float* x    = (const float*)d_in[0];
    const float* W_q  = (const float*)d_in[1];
    const float* W_k  = (const float*)d_in[2];
    const float* W_v  = (const float*)d_in[3];
    const float* fc_o = (const float*)d_in[4];
    float* out = (float*)d_out;

    bf16 *xh, *xl, *qkvh, *qkvl, *mh, *ml, *wh, *wl;
    cudaGetSymbolAddress((void**)&xh, g_xh);
    cudaGetSymbolAddress((void**)&xl, g_xl);
    cudaGetSymbolAddress((void**)&qkvh, g_qkvh);
    cudaGetSymbolAddress((void**)&qkvl, g_qkvl);
    cudaGetSymbolAddress((void**)&mh, g_mh);
    cudaGetSymbolAddress((void**)&ml, g_ml);
    cudaGetSymbolAddress((void**)&wh, g_wh);
    cudaGetSymbolAddress((void**)&wl, g_wl);

    cudaFuncSetAttribute(gemm_mma, cudaFuncAttributeMaxDynamicSharedMemorySize, GEMM_SMEM);
    cudaFuncSetAttribute(attn_mma, cudaFuncAttributeMaxDynamicSharedMemorySize, ATTN_SMEM);

    const int n2_x = MTOT * D_MODEL / 2;
    dim3 wgrid(D_MODEL / 32, D_MODEL / 32, 4);
    dim3 wblk(32, 8);

    // All conversions up front (fc_o transpose off the critical path)
    split_kernel<<<(n2_x + 255) / 256, 256>>>(x, xh, xl, n2_x);
    wT_split4<<<wgrid, wblk>>>(W_q, W_k, W_v, fc_o, wh, wl);

    // QKV: split bf16 outputs, Q pre-scaled by 1/sqrt(Hd)
    dim3 ggrid3(D_MODEL / 128, MTOT / 128, 3);  // (8, 64, 3)
    gemm_mma<<<ggrid3, 256, GEMM_SMEM>>>(xh, xl, wh, wl, nullptr, qkvh, qkvl, 0.125f);

    const size_t PL = (size_t)MTOT * D_MODEL;
    dim3 attn_grid(SEQ / 64, HEADS, BATCH);  // (32, 16, 4)
    attn_mma<<<attn_grid, 128, ATTN_SMEM>>>(qkvh, qkvl, qkvh + PL, qkvl + PL,
                                            qkvh + 2 * PL, qkvl + 2 * PL, mh, ml);

    // out-proj: fp32 output, weight slot 3
    dim3 ggrid1(D_MODEL / 128, MTOT / 128, 1);
    gemm_mma<<<ggrid1, 256, GEMM_SMEM>>>(mh, ml, wh + (size_t)3 * WSZ,
                                         wl + (size_t)3 * WSZ, out, nullptr, nullptr, 1.0f);
}

// round 10
// speedup vs baseline: 1.1478x; 1.0136x over previous
#include <cuda_runtime.h>
#include <cuda_bf16.h>
#include <math.h>
#include <stdint.h>

#define D_MODEL 1024
#define HEADS 16
#define HEAD_DIM 64
#define BATCH 4
#define SEQ 2048
#define MTOT (BATCH * SEQ) /* 8192 */
#define WSZ (D_MODEL * D_MODEL)

typedef __nv_bfloat16 bf16;

// ---- scratch (static __device__; allocation APIs forbidden) ----
__device__ bf16 g_xh[(size_t)MTOT * D_MODEL];
__device__ bf16 g_xl[(size_t)MTOT * D_MODEL];
__device__ bf16 g_qkvh[(size_t)3 * MTOT * D_MODEL];
__device__ bf16 g_qkvl[(size_t)3 * MTOT * D_MODEL];
__device__ bf16 g_mh[(size_t)MTOT * D_MODEL];
__device__ bf16 g_ml[(size_t)MTOT * D_MODEL];
__device__ bf16 g_wh[(size_t)4 * WSZ];
__device__ bf16 g_wl[(size_t)4 * WSZ];

// ============================ PTX helpers ============================
__device__ __forceinline__ uint32_t smem_u32(const void* p) {
    uint32_t a;
    asm("{ .reg .u64 t; cvta.to.shared.u64 t, %1; cvt.u32.u64 %0, t; }"
        : "=r"(a) : "l"(p));
    return a;
}
__device__ __forceinline__ void cp16(uint32_t s, const void* g) {
    asm volatile("cp.async.cg.shared.global [%0], [%1], 16;" :: "r"(s), "l"(g) : "memory");
}
__device__ __forceinline__ void cp_commit() {
    asm volatile("cp.async.commit_group;" ::: "memory");
}
template <int N> __device__ __forceinline__ void cp_wait() {
    asm volatile("cp.async.wait_group %0;" :: "n"(N) : "memory");
}
__device__ __forceinline__ void ldsm4(uint32_t* r, uint32_t addr) {
    asm volatile("ldmatrix.sync.aligned.m8n8.x4.shared.b16 {%0,%1,%2,%3}, [%4];"
                 : "=r"(r[0]), "=r"(r[1]), "=r"(r[2]), "=r"(r[3]) : "r"(addr));
}
__device__ __forceinline__ void ldsm4t(uint32_t* r, uint32_t addr) {
    asm volatile("ldmatrix.sync.aligned.m8n8.x4.trans.shared.b16 {%0,%1,%2,%3}, [%4];"
                 : "=r"(r[0]), "=r"(r[1]), "=r"(r[2]), "=r"(r[3]) : "r"(addr));
}
__device__ __forceinline__ void mma16816(float* c, const uint32_t* a,
                                         uint32_t b0, uint32_t b1) {
    asm volatile(
        "mma.sync.aligned.m16n8k16.row.col.f32.bf16.bf16.f32 "
        "{%0,%1,%2,%3},{%4,%5,%6,%7},{%8,%9},{%0,%1,%2,%3};"
        : "+f"(c[0]), "+f"(c[1]), "+f"(c[2]), "+f"(c[3])
        : "r"(a[0]), "r"(a[1]), "r"(a[2]), "r"(a[3]), "r"(b0), "r"(b1));
}
__device__ __forceinline__ uint32_t sw128(uint32_t o) { return o ^ ((o >> 3) & 0x70); }
__device__ __forceinline__ uint32_t sw64(uint32_t o)  { return o ^ ((o >> 3) & 0x30); }

// Split a float pair into packed bf16x2 hi + packed bf16x2 lo (6 ops total).
__device__ __forceinline__ uint32_t pack_split(float v0, float v1, uint32_t& lp) {
    uint32_t hp;
    asm("cvt.rn.bf16x2.f32 %0, %1, %2;" : "=r"(hp) : "f"(v1), "f"(v0));
    float h0 = __uint_as_float(hp << 16);
    float h1 = __uint_as_float(hp & 0xffff0000u);
    float l0 = v0 - h0, l1 = v1 - h1;
    asm("cvt.rn.bf16x2.f32 %0, %1, %2;" : "=r"(lp) : "f"(l1), "f"(l0));
    return hp;
}

#define LOG2E 1.4426950408889634f

// ============================ mma.sync GEMM v3 ============================
// C[M,1024] = A[M,1024] @ W. 3-term bf16 split. CTA tile 128x128, BK=32,
// 8 warps (4m x 2n), warp tile 32x64. SW64 smem rows (64B, no pad),
// 3-stage cp.async pipeline, 2 CTAs/SM (16 warps).
#define GBK 32
#define GNCHUNK (D_MODEL / GBK) /* 32 */
#define GARR 8192               /* one 128x64B array */
#define GST (4 * GARR)          /* stage: Ah,Al,Bh,Bl = 32KB */
#define GEMM_SMEM (3 * GST)     /* 98304 */

__global__ __launch_bounds__(256, 2) void gemm_mma(
    const bf16* __restrict__ Ah, const bf16* __restrict__ Al,
    const bf16* __restrict__ BhAll, const bf16* __restrict__ BlAll,
    float* __restrict__ Cf, bf16* __restrict__ ChAll, bf16* __restrict__ ClAll,
    float scale0)
{
    extern __shared__ char smem[];
    const uint32_t sb = smem_u32(smem);
    const int tid = threadIdx.x;
    const int wid = tid >> 5, lane = tid & 31;
    const int wm = wid & 3, wn = wid >> 2;
    const int rowBase = blockIdx.y * 128;
    const int colBase = blockIdx.x * 128;

    const bf16* Bh = BhAll + (size_t)blockIdx.z * WSZ;
    const bf16* Bl = BlAll + (size_t)blockIdx.z * WSZ;

    const bf16* srcAh = Ah + (size_t)rowBase * D_MODEL;
    const bf16* srcAl = Al + (size_t)rowBase * D_MODEL;
    const bf16* srcBh = Bh + (size_t)colBase * D_MODEL;
    const bf16* srcBl = Bl + (size_t)colBase * D_MODEL;

    float acc[2][8][4];
#pragma unroll
    for (int mi = 0; mi < 2; mi++)
#pragma unroll
        for (int ni = 0; ni < 8; ni++)
#pragma unroll
            for (int j = 0; j < 4; j++) acc[mi][ni][j] = 0.f;

    auto load_chunk = [&](int c, int stg) {
        const uint32_t tb = sb + stg * GST;
        const int kofs = c * GBK;
#pragma unroll
        for (int i = 0; i < 2; i++) {
            int f = i * 256 + tid;
            int row = f >> 2, cc = f & 3;
            uint32_t so = sw64((uint32_t)(row * 64 + cc * 16));
            const size_t go = (size_t)row * D_MODEL + kofs + cc * 8;
            cp16(tb + so, srcAh + go);
            cp16(tb + GARR + so, srcAl + go);
            cp16(tb + 2 * GARR + so, srcBh + go);
            cp16(tb + 3 * GARR + so, srcBl + go);
        }
    };

    const uint32_t lrow = lane & 15, lcol = lane >> 4;

    load_chunk(0, 0); cp_commit();
    load_chunk(1, 1); cp_commit();

    for (int c = 0; c < GNCHUNK; c++) {
        if (c + 1 < GNCHUNK) cp_wait<1>(); else cp_wait<0>();
        __syncthreads();
        if (c + 2 < GNCHUNK) { load_chunk(c + 2, (c + 2) % 3); cp_commit(); }

        const uint32_t tb = sb + (c % 3) * GST;
#pragma unroll
        for (int k16 = 0; k16 < 2; k16++) {
            const uint32_t kb = k16 * 32;
            uint32_t a_h[2][4], a_l[2][4], bfr[4][4];
#pragma unroll
            for (int mi = 0; mi < 2; mi++) {
                uint32_t o = (uint32_t)((wm * 32 + mi * 16 + lrow) * 64 + kb + lcol * 16);
                ldsm4(a_h[mi], tb + sw64(o));
                ldsm4(a_l[mi], tb + GARR + sw64(o));
            }
#pragma unroll
            for (int nb = 0; nb < 4; nb++) {
                uint32_t o = (uint32_t)((wn * 64 + nb * 16 + lrow) * 64 + kb + lcol * 16);
                ldsm4(bfr[nb], tb + 2 * GARR + sw64(o));
            }
#pragma unroll
            for (int nb = 0; nb < 4; nb++)
#pragma unroll
                for (int mi = 0; mi < 2; mi++) {
                    mma16816(acc[mi][2 * nb], a_h[mi], bfr[nb][0], bfr[nb][2]);
                    mma16816(acc[mi][2 * nb + 1], a_h[mi], bfr[nb][1], bfr[nb][3]);
                }
#pragma unroll
            for (int nb = 0; nb < 4; nb++)
#pragma unroll
                for (int mi = 0; mi < 2; mi++) {
                    mma16816(acc[mi][2 * nb], a_l[mi], bfr[nb][0], bfr[nb][2]);
                    mma16816(acc[mi][2 * nb + 1], a_l[mi], bfr[nb][1], bfr[nb][3]);
                }
#pragma unroll
            for (int nb = 0; nb < 4; nb++) {
                uint32_t o = (uint32_t)((wn * 64 + nb * 16 + lrow) * 64 + kb + lcol * 16);
                ldsm4(bfr[nb], tb + 3 * GARR + sw64(o));
            }
#pragma unroll
            for (int nb = 0; nb < 4; nb++)
#pragma unroll
                for (int mi = 0; mi < 2; mi++) {
                    mma16816(acc[mi][2 * nb], a_h[mi], bfr[nb][0], bfr[nb][2]);
                    mma16816(acc[mi][2 * nb + 1], a_h[mi], bfr[nb][1], bfr[nb][3]);
                }
        }
    }

    __syncthreads();

    // Epilogue
    const int g = lane >> 2, t4 = lane & 3;
    if (ChAll) {
        bf16* Ch = ChAll + (size_t)blockIdx.z * MTOT * D_MODEL;
        bf16* Cl = ClAll + (size_t)blockIdx.z * MTOT * D_MODEL;
        const float sc = (blockIdx.z == 0) ? scale0 : 1.0f;
#pragma unroll
        for (int mi = 0; mi < 2; mi++)
#pragma unroll
            for (int ni = 0; ni < 8; ni++) {
                int r = rowBase + wm * 32 + mi * 16 + g;
                int col = colBase + wn * 64 + ni * 8 + t4 * 2;
#pragma unroll
                for (int half = 0; half < 2; half++) {
                    uint32_t lp;
                    uint32_t hp = pack_split(acc[mi][ni][2 * half] * sc,
                                             acc[mi][ni][2 * half + 1] * sc, lp);
                    size_t o = (size_t)(r + 8 * half) * D_MODEL + col;
                    *(uint32_t*)&Ch[o] = hp;
                    *(uint32_t*)&Cl[o] = lp;
                }
            }
    } else {
#pragma unroll
        for (int mi = 0; mi < 2; mi++)
#pragma unroll
            for (int ni = 0; ni < 8; ni++) {
                int r = rowBase + wm * 32 + mi * 16 + g;
                int col = colBase + wn * 64 + ni * 8 + t4 * 2;
                *(float2*)&Cf[(size_t)r * D_MODEL + col] =
                    make_float2(acc[mi][ni][0], acc[mi][ni][1]);
                *(float2*)&Cf[(size_t)(r + 8) * D_MODEL + col] =
                    make_float2(acc[mi][ni][2], acc[mi][ni][3]);
            }
    }
}

// ==================== conversion kernels ====================
__global__ __launch_bounds__(256) void split_kernel(
    const float* __restrict__ in, bf16* __restrict__ hi, bf16* __restrict__ lo, int n2)
{
    int i = blockIdx.x * blockDim.x + threadIdx.x;
    if (i >= n2) return;
    float2 v = ((const float2*)in)[i];
    uint32_t lp;
    uint32_t hp = pack_split(v.x, v.y, lp);
    ((uint32_t*)hi)[i] = hp;
    ((uint32_t*)lo)[i] = lp;
}

// W [K][N] fp32 -> Wt hi/lo [N][K] bf16 (transpose + split), 4 weights via z
__global__ __launch_bounds__(256) void wT_split4(
    const float* __restrict__ W0, const float* __restrict__ W1,
    const float* __restrict__ W2, const float* __restrict__ W3,
    bf16* __restrict__ Th, bf16* __restrict__ Tl)
{
    const float* W = (blockIdx.z == 0) ? W0 : (blockIdx.z == 1) ? W1
                     : (blockIdx.z == 2) ? W2 : W3;
    Th += (size_t)blockIdx.z * WSZ;
    Tl += (size_t)blockIdx.z * WSZ;
    __shared__ float t[32][33];
    int nx = blockIdx.x * 32 + threadIdx.x;
#pragma unroll
    for (int j = 0; j < 32; j += 8)
        t[threadIdx.y + j][threadIdx.x] =
            W[(size_t)(blockIdx.y * 32 + threadIdx.y + j) * D_MODEL + nx];
    __syncthreads();
    int k = blockIdx.y * 32 + threadIdx.x;
#pragma unroll
    for (int j = 0; j < 32; j += 8) {
        int n = blockIdx.x * 32 + threadIdx.y + j;
        float v = t[threadIdx.x][threadIdx.y + j];
        bf16 h = __float2bfloat16(v);
        bf16 l = __float2bfloat16(v - __bfloat162float(h));
        Th[(size_t)n * D_MODEL + k] = h;
        Tl[(size_t)n * D_MODEL + k] = l;
    }
}

// ==================== tensor-core flash attention v5 ====================
// v4 + scalar diet: exp2-folded softmax, cvt.rn.bf16x2 paired splits.
#define KROW 128
#define KTILE (128 * KROW)          /* 16384 */
#define ATTN_SMEM (4 * KTILE)       /* 65536: Kh,Kl,Vh,Vl */

__global__ __launch_bounds__(128, 3) void attn_mma(
    const bf16* __restrict__ Qh, const bf16* __restrict__ Ql,
    const bf16* __restrict__ Kh, const bf16* __restrict__ Kl,
    const bf16* __restrict__ Vh, const bf16* __restrict__ Vl,
    bf16* __restrict__ MH, bf16* __restrict__ ML)
{
    extern __shared__ char smraw[];
    const uint32_t sb = smem_u32(smraw);
    const int tid = threadIdx.x;
    const int wid = tid >> 5, lane = tid & 31;
    const uint32_t lrow = lane & 15, lcol = lane >> 4;
    const int g = lane >> 2, t4 = lane & 3;

    const int q0 = blockIdx.x * 64;
    const int h = blockIdx.y;
    const int b = blockIdx.z;
    const size_t qrow = (size_t)b * SEQ + q0;
    const size_t krow0 = (size_t)b * SEQ;
    const int hofs = h * HEAD_DIM;

    const uint32_t skh = sb, skl = sb + KTILE;
    const uint32_t svh = sb + 2 * KTILE, svl = sb + 3 * KTILE;

    auto load_k = [&](int t) {
        const size_t kr = krow0 + (size_t)t * 128;
#pragma unroll
        for (int i = 0; i < 16; i++) {
            int f = i * 128 + tid;
            int arr = f >> 10;
            int r = (f >> 3) & 127, cg = f & 7;
            const bf16* p = arr ? Kl : Kh;
            cp16(sb + arr * KTILE + sw128((uint32_t)(r * KROW + cg * 16)),
                 p + (kr + r) * D_MODEL + hofs + cg * 8);
        }
    };
    auto load_v = [&](int t) {
        const size_t kr = krow0 + (size_t)t * 128;
#pragma unroll
        for (int i = 0; i < 16; i++) {
            int f = i * 128 + tid;
            int arr = f >> 10;
            int r = (f >> 3) & 127, cg = f & 7;
            const bf16* p = arr ? Vl : Vh;
            cp16(sb + (2 + arr) * KTILE + sw128((uint32_t)(r * KROW + cg * 16)),
                 p + (kr + r) * D_MODEL + hofs + cg * 8);
        }
    };

    load_k(0); cp_commit();
    load_v(0); cp_commit();

    uint32_t qhf[4][4], qlf[4][4];
    {
        const size_t r0 = qrow + wid * 16 + g;
        const int c0 = hofs + t4 * 2;
#pragma unroll
        for (int kc = 0; kc < 4; kc++) {
#pragma unroll
            for (int q = 0; q < 4; q++) {
                size_t r = r0 + ((q & 1) ? 8 : 0);
                int c = c0 + kc * 16 + ((q & 2) ? 8 : 0);
                qhf[kc][q] = *(const uint32_t*)&Qh[r * D_MODEL + c];
                qlf[kc][q] = *(const uint32_t*)&Ql[r * D_MODEL + c];
            }
        }
    }

    float o[8][4];
#pragma unroll
    for (int di = 0; di < 8; di++)
#pragma unroll
        for (int j = 0; j < 4; j++) o[di][j] = 0.f;
    float m_prev[2] = {-1e30f, -1e30f};
    float lsum[2] = {0.f, 0.f};

    const int NT = SEQ / 128;

    for (int t = 0; t < NT; t++) {
        cp_wait<1>();
        __syncthreads();

#pragma unroll
        for (int hf = 0; hf < 2; hf++) {
            const int rbase = hf * 64;
            float s[8][4];
#pragma unroll
            for (int ni = 0; ni < 8; ni++)
#pragma unroll
                for (int j = 0; j < 4; j++) s[ni][j] = 0.f;

#pragma unroll
            for (int kc = 0; kc < 4; kc++) {
                uint32_t kf[4][4];
#pragma unroll
                for (int np = 0; np < 4; np++)
                    ldsm4(kf[np], skh + sw128((uint32_t)((rbase + np * 16 + lrow) * KROW +
                                                         kc * 32 + lcol * 16)));
#pragma unroll
                for (int ni = 0; ni < 8; ni++) {
                    int np = ni >> 1, hl = ni & 1;
                    mma16816(s[ni], qhf[kc], kf[np][hl], kf[np][hl + 2]);
                }
#pragma unroll
                for (int ni = 0; ni < 8; ni++) {
                    int np = ni >> 1, hl = ni & 1;
                    mma16816(s[ni], qlf[kc], kf[np][hl], kf[np][hl + 2]);
                }
            }
#pragma unroll
            for (int kc = 0; kc < 4; kc++) {
                uint32_t kf[4][4];
#pragma unroll
                for (int np = 0; np < 4; np++)
                    ldsm4(kf[np], skl + sw128((uint32_t)((rbase + np * 16 + lrow) * KROW +
                                                         kc * 32 + lcol * 16)));
#pragma unroll
                for (int ni = 0; ni < 8; ni++) {
                    int np = ni >> 1, hl = ni & 1;
                    mma16816(s[ni], qhf[kc], kf[np][hl], kf[np][hl + 2]);
                }
            }

            if (hf == 1) {
                __syncthreads();
                if (t + 1 < NT) { load_k(t + 1); cp_commit(); }
            }

            // ---- online softmax (exp2-folded) ----
#pragma unroll
            for (int rg = 0; rg < 2; rg++) {
                float mx = -1e30f;
#pragma unroll
                for (int ni = 0; ni < 8; ni++)
                    mx = fmaxf(mx, fmaxf(s[ni][2 * rg], s[ni][2 * rg + 1]));
                mx = fmaxf(mx, __shfl_xor_sync(0xffffffffu, mx, 1));
                mx = fmaxf(mx, __shfl_xor_sync(0xffffffffu, mx, 2));
                float mn = fmaxf(m_prev[rg], mx);
                float mn2 = mn * LOG2E;
                float al = exp2f(fmaf(m_prev[rg], LOG2E, -mn2));
                float sum = 0.f;
#pragma unroll
                for (int ni = 0; ni < 8; ni++) {
                    float p0 = exp2f(fmaf(s[ni][2 * rg], LOG2E, -mn2));
                    float p1 = exp2f(fmaf(s[ni][2 * rg + 1], LOG2E, -mn2));
                    s[ni][2 * rg] = p0;
                    s[ni][2 * rg + 1] = p1;
                    sum += p0 + p1;
                }
                sum += __shfl_xor_sync(0xffffffffu, sum, 1);
                sum += __shfl_xor_sync(0xffffffffu, sum, 2);
                lsum[rg] = lsum[rg] * al + sum;
                m_prev[rg] = mn;
#pragma unroll
                for (int di = 0; di < 8; di++) {
                    o[di][2 * rg] *= al;
                    o[di][2 * rg + 1] *= al;
                }
            }

            if (hf == 0) {
                cp_wait<0>();
                __syncthreads();
            }

            // ---- O += P V (paired-cvt splits) ----
#pragma unroll
            for (int kc2 = 0; kc2 < 4; kc2++) {
                int j0 = 2 * kc2, j1 = j0 + 1;
                uint32_t ah[4], al4[4];
#pragma unroll
                for (int q = 0; q < 4; q++) {
                    const float* sp = (q & 2) ? s[j1] : s[j0];
                    ah[q] = pack_split(sp[(q & 1) * 2], sp[(q & 1) * 2 + 1], al4[q]);
                }
                uint32_t vhf[4][4], vlf[4][4];
#pragma unroll
                for (int dp = 0; dp < 4; dp++) {
                    uint32_t a = sw128((uint32_t)((rbase + kc2 * 16 + lrow) * KROW +
                                                  dp * 32 + lcol * 16));
                    ldsm4t(vhf[dp], svh + a);
                    ldsm4t(vlf[dp], svl + a);
                }
#pragma unroll
                for (int di = 0; di < 8; di++) {
                    int dp = di >> 1, off = (di & 1) * 2;
                    mma16816(o[di], ah, vhf[dp][off], vhf[dp][off + 1]);
                }
#pragma unroll
                for (int di = 0; di < 8; di++) {
                    int dp = di >> 1, off = (di & 1) * 2;
                    mma16816(o[di], ah, vlf[dp][off], vlf[dp][off + 1]);
                }
#pragma unroll
                for (int di = 0; di < 8; di++) {
                    int dp = di >> 1, off = (di & 1) * 2;
                    mma16816(o[di], al4, vhf[dp][off], vhf[dp][off + 1]);
                }
            }
        }

        __syncthreads();
        if (t + 1 < NT) { load_v(t + 1); cp_commit(); }
    }

    float inv_l[2] = {1.f / lsum[0], 1.f / lsum[1]};
#pragma unroll
    for (int di = 0; di < 8; di++) {
#pragma unroll
        for (int rg = 0; rg < 2; rg++) {
            uint32_t lp;
            uint32_t hp = pack_split(o[di][2 * rg] * inv_l[rg],
                                     o[di][2 * rg + 1] * inv_l[rg], lp);
            size_t idx = (qrow + wid * 16 + g + 8 * rg) * D_MODEL + hofs + di * 8 + t4 * 2;
            *(uint32_t*)&MH[idx] = hp;
            *(uint32_t*)&ML[idx] = lp;
        }
    }
}

// ---------------------------------------------------------------------------
extern "C" void kernel_launch(void* const* d_in, const int* in_sizes, int n_in,
                              void* d_out, int out_size)
{
    (void)in_sizes; (void)n_in; (void)out_size;
    const float* x    = (const float*)d_in[0];
    const float* W_q  = (const float*)d_in[1];
    const float* W_k  = (const float*)d_in[2];
    const float* W_v  = (const float*)d_in[3];
    const float* fc_o = (const float*)d_in[4];
    float* out = (float*)d_out;

    bf16 *xh, *xl, *qkvh, *qkvl, *mh, *ml, *wh, *wl;
    cudaGetSymbolAddress((void**)&xh, g_xh);
    cudaGetSymbolAddress((void**)&xl, g_xl);
    cudaGetSymbolAddress((void**)&qkvh, g_qkvh);
    cudaGetSymbolAddress((void**)&qkvl, g_qkvl);
    cudaGetSymbolAddress((void**)&mh, g_mh);
    cudaGetSymbolAddress((void**)&ml, g_ml);
    cudaGetSymbolAddress((void**)&wh, g_wh);
    cudaGetSymbolAddress((void**)&wl, g_wl);

    cudaFuncSetAttribute(gemm_mma, cudaFuncAttributeMaxDynamicSharedMemorySize, GEMM_SMEM);
    cudaFuncSetAttribute(attn_mma, cudaFuncAttributeMaxDynamicSharedMemorySize, ATTN_SMEM);

    const int n2_x = MTOT * D_MODEL / 2;
    dim3 wgrid(D_MODEL / 32, D_MODEL / 32, 4);
    dim3 wblk(32, 8);

    split_kernel<<<(n2_x + 255) / 256, 256>>>(x, xh, xl, n2_x);
    wT_split4<<<wgrid, wblk>>>(W_q, W_k, W_v, fc_o, wh, wl);

    dim3 ggrid3(D_MODEL / 128, MTOT / 128, 3);
    gemm_mma<<<ggrid3, 256, GEMM_SMEM>>>(xh, xl, wh, wl, nullptr, qkvh, qkvl, 0.125f);

    const size_t PL = (size_t)MTOT * D_MODEL;
    dim3 attn_grid(SEQ / 64, HEADS, BATCH);
    attn_mma<<<attn_grid, 128, ATTN_SMEM>>>(qkvh, qkvl, qkvh + PL, qkvl + PL,
                                            qkvh + 2 * PL, qkvl + 2 * PL, mh, ml);

    dim3 ggrid1(D_MODEL / 128, MTOT / 128, 1);
    gemm_mma<<<ggrid1, 256, GEMM_SMEM>>>(mh, ml, wh + (size_t)3 * WSZ,
                                         wl + (size_t)3 * WSZ, out, nullptr, nullptr, 1.0f);
}